// round 8
// baseline (speedup 1.0000x reference)
#include <cuda_runtime.h>
#include <cuda_bf16.h>
#include <cuda_fp16.h>
#include <math.h>

#define Bv 8
#define Lv 512
#define Kv 30
#define Hv 128
#define NINv 384
#define FEATv 72
#define EPSv 1e-8f

#define NSITE (Bv * Lv)          // 4096
#define MPAD (NSITE * 32)        // 131072 padded rows (32 edges/site)
#define KA 480                   // A width: 384 hE + 72 feats + 24 zero
#define NCH 15                   // 480/32 k-chunks

// ------------------------- global scratch (static, no allocs) -------------
__device__ float g_feat[(size_t)MPAD * 96];     // feats (A cols 384..479), fp32
__device__ float g_C3[(size_t)MPAD * Hv];
__device__ float g_bias1[(size_t)NSITE * Hv];
__device__ __half g_W1f[KA * Hv];
__device__ __half g_W2f[Hv * Hv];
__device__ __half g_W3f[Hv * Hv];

__device__ __forceinline__ float geluf(float x) {
    return 0.5f * x * (1.0f + erff(x * 0.7071067811865476f));
}
// pack two floats as fp16x2 (high part)
__device__ __forceinline__ unsigned pack2h(float a, float b) {
    __half2 v = __floats2half2_rn(a, b);
    return *(unsigned*)&v;
}
// pack two fp16 residuals
__device__ __forceinline__ unsigned pack2l(float a, float b) {
    float ra = a - __half2float(__float2half_rn(a));
    float rb = b - __half2float(__float2half_rn(b));
    __half2 v = __floats2half2_rn(ra, rb);
    return *(unsigned*)&v;
}

// ------------------------- small prep kernels -----------------------------
__global__ void wprep_kernel(const float* __restrict__ W1,
                             const float* __restrict__ W2,
                             const float* __restrict__ W3) {
    int idx = blockIdx.x * 256 + threadIdx.x;
    if (idx < KA * Hv) {
        int j = idx / Hv, c = idx % Hv;
        float v = (j < 456) ? W1[(Hv + j) * Hv + c] : 0.0f;
        g_W1f[idx] = __float2half_rn(v);
    } else if (idx < KA * Hv + Hv * Hv) {
        int i2 = idx - KA * Hv;
        g_W2f[i2] = __float2half_rn(W2[i2]);
    } else if (idx < KA * Hv + 2 * Hv * Hv) {
        int i3 = idx - KA * Hv - Hv * Hv;
        g_W3f[i3] = __float2half_rn(W3[i3]);
    }
}

// node-term bias: bias1[site][c] = b1[c] + sum_r hV[site,r] * W1[r,c]  (exact fp32)
__global__ __launch_bounds__(128) void bias1_kernel(const float* __restrict__ hV,
                                                    const float* __restrict__ W1,
                                                    const float* __restrict__ b1) {
    extern __shared__ float bsm[];
    float* sW = bsm;
    float* shv = bsm + 16384;
    int c = threadIdx.x;
    for (int i = c; i < 16384; i += 128) sW[i] = W1[i];
    __syncthreads();
    for (int site = blockIdx.x; site < NSITE; site += gridDim.x) {
        shv[c] = hV[(size_t)site * Hv + c];
        __syncthreads();
        float acc = b1[c];
        #pragma unroll 8
        for (int r = 0; r < Hv; r++) acc = fmaf(shv[r], sW[r * Hv + c], acc);
        g_bias1[(size_t)site * Hv + c] = acc;
        __syncthreads();
    }
}

__device__ __forceinline__ void make_frame(const float* __restrict__ x,
                                           float* __restrict__ R,
                                           float* __restrict__ t) {
    float Nx = x[0], Ny = x[1], Nz = x[2];
    float CAx = x[3], CAy = x[4], CAz = x[5];
    float Cx = x[6], Cy = x[7], Cz = x[8];
    float e0x = CAx - Nx, e0y = CAy - Ny, e0z = CAz - Nz;
    float inv = 1.0f / sqrtf(e0x * e0x + e0y * e0y + e0z * e0z + EPSv);
    e0x *= inv; e0y *= inv; e0z *= inv;
    float e1x = Cx - CAx, e1y = Cy - CAy, e1z = Cz - CAz;
    float d = e0x * e1x + e0y * e1y + e0z * e1z;
    e1x -= e0x * d; e1y -= e0y * d; e1z -= e0z * d;
    inv = 1.0f / sqrtf(e1x * e1x + e1y * e1y + e1z * e1z + EPSv);
    e1x *= inv; e1y *= inv; e1z *= inv;
    float e2x = e0y * e1z - e0z * e1y;
    float e2y = e0z * e1x - e0x * e1z;
    float e2z = e0x * e1y - e0y * e1x;
    R[0] = e0x; R[1] = e1x; R[2] = e2x;
    R[3] = e0y; R[4] = e1y; R[5] = e2y;
    R[6] = e0z; R[7] = e1z; R[8] = e2z;
    t[0] = CAx; t[1] = CAy; t[2] = CAz;
}

// ---------------------------------------------------------------------------
// geoFeat: 2 sites per block, 256 threads; shared Wp stage.
// per-half layout (floats): hvp 3870 | pln 720 | R 270 | T 90 | npg 720 | feat 2160
// ---------------------------------------------------------------------------
#define GH_HVP  0
#define GH_PLN  3870
#define GH_R    4590
#define GH_T    4860
#define GH_NPG  4950
#define GH_FEAT 5670
#define GH_SIZE 7830
#define GEOF_SMEM ((3072 + 2 * GH_SIZE) * 4)   // 74928 bytes

__global__ void __launch_bounds__(256) geoFeat_kernel(
    const float* __restrict__ hE,
    const float* __restrict__ Xn,
    const float* __restrict__ Wp,
    const float* __restrict__ bp)
{
    extern __shared__ float gs[];
    int tid = threadIdx.x;
    int hf = tid >> 7, t = tid & 127;
    int site = blockIdx.x * 2 + hf;

    float* WP = gs;
    float* base = gs + 3072 + hf * GH_SIZE;

    for (int i = tid; i < 3072; i += 256) WP[i] = Wp[i];
    for (int i = t; i < 30 * 128; i += 128) {
        int k = i >> 7, j = i & 127;
        base[GH_HVP + k * 129 + j] = hE[((size_t)(site * Kv + k)) * NINv + 256 + j];
    }
    if (t < Kv) make_frame(Xn + ((size_t)(site * Kv + t)) * 9,
                           base + GH_R + t * 9, base + GH_T + t * 3);
    __syncthreads();

    // p_ln[30][24]
    if (t < 120) {
        int k = t % 30, g = t / 30;
        float acc[6];
        #pragma unroll
        for (int j = 0; j < 6; j++) acc[j] = bp[g * 6 + j];
        const float* e = base + GH_HVP + k * 129;
        const float* wbase = WP + g * 6;
        #pragma unroll 4
        for (int i = 0; i < 128; i++) {
            float h = e[i];
            const float* wr = wbase + i * 24;
            float2 w01 = *(const float2*)(wr);
            float2 w23 = *(const float2*)(wr + 2);
            float2 w45 = *(const float2*)(wr + 4);
            acc[0] = fmaf(h, w01.x, acc[0]);
            acc[1] = fmaf(h, w01.y, acc[1]);
            acc[2] = fmaf(h, w23.x, acc[2]);
            acc[3] = fmaf(h, w23.y, acc[3]);
            acc[4] = fmaf(h, w45.x, acc[4]);
            acc[5] = fmaf(h, w45.y, acc[5]);
        }
        #pragma unroll
        for (int j = 0; j < 6; j++) base[GH_PLN + k * 24 + g * 6 + j] = acc[j];
    }
    __syncthreads();

    if (t < Kv) {
        int k = t;
        const float* R = base + GH_R + k * 9;
        const float* tt = base + GH_T + k * 3;
        const float* pl = base + GH_PLN + k * 24;
        #pragma unroll
        for (int n = 0; n < 8; n++)
            #pragma unroll
            for (int i = 0; i < 3; i++)
                base[GH_NPG + k * 24 + n * 3 + i] =
                    tt[i] + R[i * 3] * pl[n * 3] + R[i * 3 + 1] * pl[n * 3 + 1]
                          + R[i * 3 + 2] * pl[n * 3 + 2];
    }
    __syncthreads();

    if (t < Kv) {
        int k = t;
        float* f = base + GH_FEAT + k * 72;
        const float* pl0 = base + GH_PLN;
        const float* pg  = base + GH_NPG;
        const float* R0  = base + GH_R;
        const float* t0  = base + GH_T;
        const float* ng  = base + GH_NPG + k * 24;
        #pragma unroll
        for (int n = 0; n < 8; n++) {
            float p0 = pl0[n * 3], p1 = pl0[n * 3 + 1], p2 = pl0[n * 3 + 2];
            f[n * 3] = p0; f[n * 3 + 1] = p1; f[n * 3 + 2] = p2;
            f[24 + n] = sqrtf(p0 * p0 + p1 * p1 + p2 * p2 + EPSv);
            float d0 = ng[n * 3]     - t0[0];
            float d1 = ng[n * 3 + 1] - t0[1];
            float d2 = ng[n * 3 + 2] - t0[2];
            float n0 = R0[0] * d0 + R0[3] * d1 + R0[6] * d2;
            float n1 = R0[1] * d0 + R0[4] * d1 + R0[7] * d2;
            float n2 = R0[2] * d0 + R0[5] * d1 + R0[8] * d2;
            f[32 + n * 3] = n0; f[32 + n * 3 + 1] = n1; f[32 + n * 3 + 2] = n2;
            f[56 + n] = sqrtf(n0 * n0 + n1 * n1 + n2 * n2 + EPSv);
            float gx = pg[n * 3]     - ng[n * 3];
            float gy = pg[n * 3 + 1] - ng[n * 3 + 1];
            float gz = pg[n * 3 + 2] - ng[n * 3 + 2];
            f[64 + n] = sqrtf(gx * gx + gy * gy + gz * gz + EPSv);
        }
    }
    __syncthreads();

    for (int i = t; i < 30 * 96; i += 128) {
        int k = i / 96, col = i - k * 96;
        float v = (col < 72) ? base[GH_FEAT + k * 72 + col] : 0.0f;
        g_feat[((size_t)(site * 32 + k)) * 96 + col] = v;
    }
}

// ---------------------------------------------------------------------------
// Fused GEMM, fp16 2-pass: A split fp16 (hi+lo), weights single fp16.
// C3 = gelu(gelu(A@W1+bias1)@W2+b2)@W3 + b3.
// 256 thr, M-tile 128 = 4 sites x 32 padded edges, 2 CTAs/SM.
// smem: Abuf 2x20480 [0,40960) | Wst 2x8704 [40960,58368) | spill 32768
//       W2/W3 (34816 ea) reuse [0,34816) after phase 1 / phase 2.
// ---------------------------------------------------------------------------
#define ABUF(i)  ((i) * 20480)
#define WST(i)   (40960 + (i) * 8704)
#define OFF_W    0
#define OFF_SPILL 58368
#define GEMM_SMEM (OFF_SPILL + 32768)   // 91136

__device__ __forceinline__ void cpasync16(unsigned dst, const void* src) {
    asm volatile("cp.async.cg.shared.global [%0], [%1], 16;\n" :: "r"(dst), "l"(src));
}
__device__ __forceinline__ void ldm_x4(unsigned* r, unsigned addr) {
    asm volatile("ldmatrix.sync.aligned.m8n8.x4.shared.b16 {%0,%1,%2,%3}, [%4];"
        : "=r"(r[0]), "=r"(r[1]), "=r"(r[2]), "=r"(r[3]) : "r"(addr));
}
__device__ __forceinline__ void ldm_x4_t(unsigned* r, unsigned addr) {
    asm volatile("ldmatrix.sync.aligned.m8n8.x4.trans.shared.b16 {%0,%1,%2,%3}, [%4];"
        : "=r"(r[0]), "=r"(r[1]), "=r"(r[2]), "=r"(r[3]) : "r"(addr));
}
__device__ __forceinline__ void mma_f16(float* d, const unsigned* a, unsigned b0, unsigned b1) {
    asm volatile("mma.sync.aligned.m16n8k16.row.col.f32.f16.f16.f32 "
        "{%0,%1,%2,%3}, {%4,%5,%6,%7}, {%8,%9}, {%0,%1,%2,%3};"
        : "+f"(d[0]), "+f"(d[1]), "+f"(d[2]), "+f"(d[3])
        : "r"(a[0]), "r"(a[1]), "r"(a[2]), "r"(a[3]), "r"(b0), "r"(b1));
}
__device__ __forceinline__ void sts128(unsigned addr, const unsigned* v) {
    asm volatile("st.shared.v4.b32 [%0], {%1,%2,%3,%4};"
        :: "r"(addr), "r"(v[0]), "r"(v[1]), "r"(v[2]), "r"(v[3]));
}
__device__ __forceinline__ void lds128(unsigned* v, unsigned addr) {
    asm volatile("ld.shared.v4.b32 {%0,%1,%2,%3}, [%4];"
        : "=r"(v[0]), "=r"(v[1]), "=r"(v[2]), "=r"(v[3]) : "r"(addr));
}

// W1 k-chunk loader: 32 rows of W1f into WST(st) (stride 136 halves)
__device__ __forceinline__ void wload_chunk(unsigned sbase, int st,
                                            const __half* __restrict__ W1f,
                                            int kc, int tid) {
    unsigned wst = sbase + WST(st);
    #pragma unroll
    for (int i = 0; i < 2; i++) {
        int tt = tid + i * 256;
        int rb = tt >> 4, sg = tt & 15;
        cpasync16(wst + (rb * 136 + sg * 8) * 2, W1f + (size_t)(kc + rb) * Hv + sg * 8);
    }
    asm volatile("cp.async.commit_group;\n" ::);
}

// Full 128x128 fp16 weight into [off, off+34816)
__device__ __forceinline__ void load_weight(unsigned sbase, unsigned off,
                                            const __half* __restrict__ src, int tid) {
    #pragma unroll
    for (int i = 0; i < 8; i++) {
        int idx = tid + i * 256;
        int r = idx >> 4, s = idx & 15;
        cpasync16(sbase + off + (r * 136 + s * 8) * 2, src + (size_t)r * Hv + s * 8);
    }
}

__global__ __launch_bounds__(256, 2) void fusedgemm_kernel(
    const float* __restrict__ hE, const float* __restrict__ feat,
    const __half* __restrict__ W1f, const __half* __restrict__ W2f,
    const __half* __restrict__ W3f,
    const float* __restrict__ bias1,
    const float* __restrict__ b2, const float* __restrict__ b3,
    float* __restrict__ C3)
{
    extern __shared__ __align__(16) unsigned char gsm[];
    unsigned sbase = (unsigned)__cvta_generic_to_shared(gsm);

    int tid = threadIdx.x;
    int lane = tid & 31, w = tid >> 5;
    int rowBase = blockIdx.x * 128;
    unsigned spill_base = sbase + OFF_SPILL + w * 4096 + lane * 16;

    // A loader identity: thread covers row arow, 16 cols at half16*16
    int arow = tid >> 1, half16 = tid & 1;
    int gr = rowBase + arow;
    int asite = gr >> 5;
    int ak = gr & 31; if (ak > 29) ak = 29;
    const float* hE_row = hE + ((size_t)(asite * Kv + ak)) * NINv + half16 * 16;
    const float* ft_row = feat + ((size_t)(asite * 32 + ak)) * 96 + half16 * 16;

    float4 f0, f1, f2, f3;
    #define LDA(cc) do { \
        const float4* s4 = (const float4*)(((cc) < 12) ? (hE_row + (cc) * 32) \
                                                       : (ft_row + ((cc) - 12) * 32)); \
        f0 = s4[0]; f1 = s4[1]; f2 = s4[2]; f3 = s4[3]; \
    } while (0)

    #define CVTSTS(buf) do { \
        unsigned uh[8], ul[8]; \
        uh[0] = pack2h(f0.x, f0.y); ul[0] = pack2l(f0.x, f0.y); \
        uh[1] = pack2h(f0.z, f0.w); ul[1] = pack2l(f0.z, f0.w); \
        uh[2] = pack2h(f1.x, f1.y); ul[2] = pack2l(f1.x, f1.y); \
        uh[3] = pack2h(f1.z, f1.w); ul[3] = pack2l(f1.z, f1.w); \
        uh[4] = pack2h(f2.x, f2.y); ul[4] = pack2l(f2.x, f2.y); \
        uh[5] = pack2h(f2.z, f2.w); ul[5] = pack2l(f2.z, f2.w); \
        uh[6] = pack2h(f3.x, f3.y); ul[6] = pack2l(f3.x, f3.y); \
        uh[7] = pack2h(f3.z, f3.w); ul[7] = pack2l(f3.z, f3.w); \
        unsigned ab = sbase + ABUF(buf) + (unsigned)((arow * 40 + half16 * 16) * 2); \
        sts128(ab, uh); sts128(ab + 16, uh + 4); \
        sts128(ab + 10240, ul); sts128(ab + 10240 + 16, ul + 4); \
    } while (0)

    float acc[16][4];
    #pragma unroll
    for (int t = 0; t < 16; t++)
        #pragma unroll
        for (int q = 0; q < 4; q++) acc[t][q] = 0.0f;

    // prologue
    wload_chunk(sbase, 0, W1f, 0, tid);
    wload_chunk(sbase, 1, W1f, 32, tid);
    LDA(0);
    CVTSTS(0);

    // -------- phase 1: A @ W1, K=480, fp16 2-pass --------
    for (int c = 0; c < NCH; c++) {
        if (c + 1 < NCH) { asm volatile("cp.async.wait_group 1;\n" ::); }
        else             { asm volatile("cp.async.wait_group 0;\n" ::); }
        __syncthreads();

        if (c + 1 < NCH) LDA(c + 1);

        unsigned abuf = sbase + ABUF(c & 1);
        unsigned wst  = sbase + WST(c & 1);
        #pragma unroll
        for (int kk = 0; kk < 32; kk += 16) {
            unsigned aH[4], aL[4];
            {
                int row = w * 16 + (lane & 15);
                unsigned off = (unsigned)((row * 40 + kk + ((lane >> 4) << 3)) * 2);
                ldm_x4(aH, abuf + off);
                ldm_x4(aL, abuf + 10240 + off);
            }
            #pragma unroll
            for (int nb = 0; nb < 8; nb++) {
                unsigned offb = (unsigned)(((kk + (lane & 15)) * 136 + nb * 16 + ((lane >> 4) << 3)) * 2);
                unsigned bh[4];
                ldm_x4_t(bh, wst + offb);
                mma_f16(acc[2 * nb],     aH, bh[0], bh[1]);
                mma_f16(acc[2 * nb],     aL, bh[0], bh[1]);
                mma_f16(acc[2 * nb + 1], aH, bh[2], bh[3]);
                mma_f16(acc[2 * nb + 1], aL, bh[2], bh[3]);
            }
        }

        if (c + 1 < NCH) CVTSTS((c + 1) & 1);
        __syncthreads();
        if (c + 2 < NCH) wload_chunk(sbase, c & 1, W1f, (c + 2) * 32, tid);
    }

    // W2 into [0, 34816) — A buffers dead now
    load_weight(sbase, OFF_W, W2f, tid);
    asm volatile("cp.async.commit_group;\n" ::);

    // phase-1 epilogue: + bias1(site), gelu, split (lows -> smem spill)
    int r0 = w * 16 + (lane >> 2);
    int r1 = r0 + 8;
    const float* bs0 = bias1 + (size_t)((rowBase + r0) >> 5) * Hv;
    const float* bs1 = bias1 + (size_t)((rowBase + r1) >> 5) * Hv;

    unsigned a_h[16][2];
    #pragma unroll
    for (int q = 0; q < 8; q++) {
        unsigned lo[4];
        #pragma unroll
        for (int h2 = 0; h2 < 2; h2++) {
            int t = 2 * q + h2;
            int col = t * 8 + ((lane & 3) << 1);
            float2 c0 = *(const float2*)(bs0 + col);
            float2 c1 = *(const float2*)(bs1 + col);
            float v00 = geluf(acc[t][0] + c0.x);
            float v01 = geluf(acc[t][1] + c0.y);
            float v10 = geluf(acc[t][2] + c1.x);
            float v11 = geluf(acc[t][3] + c1.y);
            a_h[t][0] = pack2h(v00, v01);
            lo[h2 * 2]     = pack2l(v00, v01);
            a_h[t][1] = pack2h(v10, v11);
            lo[h2 * 2 + 1] = pack2l(v10, v11);
            acc[t][0] = 0.0f; acc[t][1] = 0.0f; acc[t][2] = 0.0f; acc[t][3] = 0.0f;
        }
        sts128(spill_base + q * 512, lo);
    }
    asm volatile("cp.async.wait_group 0;\n" ::);
    __syncthreads();

    // -------- phase 2: C1 @ W2 (fp16 2-pass) --------
    #pragma unroll
    for (int q = 0; q < 8; q++) {
        unsigned aH[4] = { a_h[2 * q][0], a_h[2 * q][1], a_h[2 * q + 1][0], a_h[2 * q + 1][1] };
        unsigned aL[4];
        lds128(aL, spill_base + q * 512);
        #pragma unroll
        for (int nb = 0; nb < 8; nb++) {
            unsigned offb = (unsigned)(((q * 16 + (lane & 15)) * 136 + nb * 16 + ((lane >> 4) << 3)) * 2);
            unsigned bh[4];
            ldm_x4_t(bh, sbase + OFF_W + offb);
            mma_f16(acc[2 * nb],     aH, bh[0], bh[1]);
            mma_f16(acc[2 * nb],     aL, bh[0], bh[1]);
            mma_f16(acc[2 * nb + 1], aH, bh[2], bh[3]);
            mma_f16(acc[2 * nb + 1], aL, bh[2], bh[3]);
        }
    }
    __syncthreads();   // all warps done reading W2
    load_weight(sbase, OFF_W, W3f, tid);
    asm volatile("cp.async.commit_group;\n" ::);

    // phase-2 epilogue: + b2, gelu, split
    #pragma unroll
    for (int q = 0; q < 8; q++) {
        unsigned lo[4];
        #pragma unroll
        for (int h2 = 0; h2 < 2; h2++) {
            int t = 2 * q + h2;
            int col = t * 8 + ((lane & 3) << 1);
            float2 bb = *(const float2*)(b2 + col);
            float v00 = geluf(acc[t][0] + bb.x);
            float v01 = geluf(acc[t][1] + bb.y);
            float v10 = geluf(acc[t][2] + bb.x);
            float v11 = geluf(acc[t][3] + bb.y);
            a_h[t][0] = pack2h(v00, v01);
            lo[h2 * 2]     = pack2l(v00, v01);
            a_h[t][1] = pack2h(v10, v11);
            lo[h2 * 2 + 1] = pack2l(v10, v11);
            acc[t][0] = 0.0f; acc[t][1] = 0.0f; acc[t][2] = 0.0f; acc[t][3] = 0.0f;
        }
        sts128(spill_base + q * 512, lo);
    }
    asm volatile("cp.async.wait_group 0;\n" ::);
    __syncthreads();

    // -------- phase 3: C2 @ W3 (fp16 2-pass) --------
    #pragma unroll
    for (int q = 0; q < 8; q++) {
        unsigned aH[4] = { a_h[2 * q][0], a_h[2 * q][1], a_h[2 * q + 1][0], a_h[2 * q + 1][1] };
        unsigned aL[4];
        lds128(aL, spill_base + q * 512);
        #pragma unroll
        for (int nb = 0; nb < 8; nb++) {
            unsigned offb = (unsigned)(((q * 16 + (lane & 15)) * 136 + nb * 16 + ((lane >> 4) << 3)) * 2);
            unsigned bh[4];
            ldm_x4_t(bh, sbase + OFF_W + offb);
            mma_f16(acc[2 * nb],     aH, bh[0], bh[1]);
            mma_f16(acc[2 * nb],     aL, bh[0], bh[1]);
            mma_f16(acc[2 * nb + 1], aH, bh[2], bh[3]);
            mma_f16(acc[2 * nb + 1], aL, bh[2], bh[3]);
        }
    }

    // final epilogue: + b3, store fp32 C3
    #pragma unroll
    for (int t = 0; t < 16; t++) {
        int col = t * 8 + ((lane & 3) << 1);
        float2 bb = *(const float2*)(b3 + col);
        float2 v0; v0.x = acc[t][0] + bb.x; v0.y = acc[t][1] + bb.y;
        float2 v1; v1.x = acc[t][2] + bb.x; v1.y = acc[t][3] + bb.y;
        *(float2*)(C3 + (size_t)(rowBase + r0) * Hv + col) = v0;
        *(float2*)(C3 + (size_t)(rowBase + r1) * Hv + col) = v1;
    }
    #undef LDA
    #undef CVTSTS
}

// ---------------------------------------------------------------------------
// Final: masked mean over k + LN1 + FFN + LN2 + masked out. 8 sites/block.
// ---------------------------------------------------------------------------
#define SPB 8
__global__ __launch_bounds__(128) void final_kernel(
    const float* __restrict__ hV, const float* __restrict__ maskV,
    const float* __restrict__ maskA,
    const float* __restrict__ Wi, const float* __restrict__ bi,
    const float* __restrict__ Wo, const float* __restrict__ bo,
    const float* __restrict__ g1, const float* __restrict__ be1,
    const float* __restrict__ g2, const float* __restrict__ be2,
    float* __restrict__ out)
{
    __shared__ float s_h[SPB][Hv];
    __shared__ float s_f[SPB][4 * Hv];
    __shared__ float s_red[8];
    int c = threadIdx.x;
    int base_site = blockIdx.x * SPB;

    for (int s = 0; s < SPB; s++) {
        int site = base_site + s;
        const float* c3 = g_C3 + (size_t)site * 32 * Hv + c;
        const float* ma = maskA + (size_t)site * Kv;
        float nm = 0.0f;
        #pragma unroll
        for (int k = 0; k < Kv; k++) nm += c3[k * Hv] * ma[k];
        nm *= (1.0f / (float)Kv);
        float xv = hV[(size_t)site * Hv + c] + nm;
        float sum = xv, sq = xv * xv;
        #pragma unroll
        for (int o = 16; o; o >>= 1) {
            sum += __shfl_xor_sync(0xffffffffu, sum, o);
            sq  += __shfl_xor_sync(0xffffffffu, sq, o);
        }
        if ((c & 31) == 0) { s_red[c >> 5] = sum; s_red[4 + (c >> 5)] = sq; }
        __syncthreads();
        sum = s_red[0] + s_red[1] + s_red[2] + s_red[3];
        sq  = s_red[4] + s_red[5] + s_red[6] + s_red[7];
        float mean = sum * (1.0f / Hv);
        float var  = sq * (1.0f / Hv) - mean * mean;
        s_h[s][c] = (xv - mean) * rsqrtf(var + 1e-5f) * g1[c] + be1[c];
        __syncthreads();
    }

    float hi[SPB][4];
    #pragma unroll
    for (int s = 0; s < SPB; s++) {
        hi[s][0] = bi[c];        hi[s][1] = bi[c + 128];
        hi[s][2] = bi[c + 256];  hi[s][3] = bi[c + 384];
    }
    for (int r = 0; r < Hv; r++) {
        const float* wr = Wi + (size_t)r * 512;
        float w0 = wr[c], w1 = wr[c + 128], w2 = wr[c + 256], w3 = wr[c + 384];
        #pragma unroll
        for (int s = 0; s < SPB; s++) {
            float hv = s_h[s][r];
            hi[s][0] = fmaf(hv, w0, hi[s][0]);
            hi[s][1] = fmaf(hv, w1, hi[s][1]);
            hi[s][2] = fmaf(hv, w2, hi[s][2]);
            hi[s][3] = fmaf(hv, w3, hi[s][3]);
        }
    }
    #pragma unroll
    for (int s = 0; s < SPB; s++) {
        s_f[s][c]       = geluf(hi[s][0]);
        s_f[s][c + 128] = geluf(hi[s][1]);
        s_f[s][c + 256] = geluf(hi[s][2]);
        s_f[s][c + 384] = geluf(hi[s][3]);
    }
    __syncthreads();

    float d[SPB];
    #pragma unroll
    for (int s = 0; s < SPB; s++) d[s] = bo[c];
    for (int j = 0; j < 512; j++) {
        float w = Wo[(size_t)j * Hv + c];
        #pragma unroll
        for (int s = 0; s < SPB; s++) d[s] = fmaf(s_f[s][j], w, d[s]);
    }

    for (int s = 0; s < SPB; s++) {
        int site = base_site + s;
        float x2 = s_h[s][c] + d[s];
        float sum = x2, sq = x2 * x2;
        #pragma unroll
        for (int o = 16; o; o >>= 1) {
            sum += __shfl_xor_sync(0xffffffffu, sum, o);
            sq  += __shfl_xor_sync(0xffffffffu, sq, o);
        }
        if ((c & 31) == 0) { s_red[c >> 5] = sum; s_red[4 + (c >> 5)] = sq; }
        __syncthreads();
        sum = s_red[0] + s_red[1] + s_red[2] + s_red[3];
        sq  = s_red[4] + s_red[5] + s_red[6] + s_red[7];
        float mean = sum * (1.0f / Hv);
        float var  = sq * (1.0f / Hv) - mean * mean;
        float h2 = (x2 - mean) * rsqrtf(var + 1e-5f) * g2[c] + be2[c];
        out[(size_t)site * Hv + c] = maskV[site] * h2;
        __syncthreads();
    }
}

// ---------------------------------------------------------------------------

extern "C" void kernel_launch(void* const* d_in, const int* in_sizes, int n_in,
                              void* d_out, int out_size) {
    const float* hV    = (const float*)d_in[0];
    const float* hE    = (const float*)d_in[1];
    const float* Xn    = (const float*)d_in[3];
    const float* maskV = (const float*)d_in[4];
    const float* maskA = (const float*)d_in[5];
    const float* Wp    = (const float*)d_in[6];
    const float* bp    = (const float*)d_in[7];
    const float* W1    = (const float*)d_in[8];
    const float* b1    = (const float*)d_in[9];
    const float* W2    = (const float*)d_in[10];
    const float* b2    = (const float*)d_in[11];
    const float* W3    = (const float*)d_in[12];
    const float* b3    = (const float*)d_in[13];
    const float* Wi    = (const float*)d_in[14];
    const float* bi    = (const float*)d_in[15];
    const float* Wo    = (const float*)d_in[16];
    const float* bo    = (const float*)d_in[17];
    const float* g1    = (const float*)d_in[18];
    const float* be1   = (const float*)d_in[19];
    const float* g2    = (const float*)d_in[20];
    const float* be2   = (const float*)d_in[21];
    float* out = (float*)d_out;

    cudaFuncSetAttribute(fusedgemm_kernel, cudaFuncAttributeMaxDynamicSharedMemorySize, GEMM_SMEM);
    cudaFuncSetAttribute(bias1_kernel, cudaFuncAttributeMaxDynamicSharedMemorySize, 66048);
    cudaFuncSetAttribute(geoFeat_kernel, cudaFuncAttributeMaxDynamicSharedMemorySize, GEOF_SMEM);

    static void *pFeat = nullptr, *pC3, *pB1, *pW1f, *pW2f, *pW3f;
    if (!pFeat) {
        cudaGetSymbolAddress(&pFeat, g_feat);
        cudaGetSymbolAddress(&pC3, g_C3);   cudaGetSymbolAddress(&pB1, g_bias1);
        cudaGetSymbolAddress(&pW1f, g_W1f);
        cudaGetSymbolAddress(&pW2f, g_W2f);
        cudaGetSymbolAddress(&pW3f, g_W3f);
    }

    wprep_kernel<<<(KA * Hv + 2 * Hv * Hv + 255) / 256, 256>>>(W1, W2, W3);
    bias1_kernel<<<512, 128, 66048>>>(hV, W1, b1);
    geoFeat_kernel<<<NSITE / 2, 256, GEOF_SMEM>>>(hE, Xn, Wp, bp);

    fusedgemm_kernel<<<MPAD / 128, 256, GEMM_SMEM>>>(
        hE, (const float*)pFeat,
        (const __half*)pW1f, (const __half*)pW2f, (const __half*)pW3f,
        (const float*)pB1, b2, b3, (float*)pC3);

    final_kernel<<<NSITE / SPB, 128>>>(hV, maskV, maskA, Wi, bi, Wo, bo,
                                       g1, be1, g2, be2, out);
}

// round 11
// speedup vs baseline: 1.1221x; 1.1221x over previous
#include <cuda_runtime.h>
#include <cuda_fp16.h>
#include <math.h>

#define Bv 8
#define Lv 512
#define Kv 30
#define Hv 128
#define NINv 384
#define EPSv 1e-8f

#define NSITE (Bv * Lv)          // 4096
#define MPAD (NSITE * 32)        // 131072 padded rows (32 edges/site)
#define KA 480                   // A width: 384 hE + 72 feats + 24 zero
#define NCH 15                   // 480/32 k-chunks

// ------------------------- global scratch (static, no allocs) -------------
__device__ float g_feat[(size_t)MPAD * 96];     // feats (A cols 384..479), fp32
__device__ float g_C3[(size_t)MPAD * Hv];
__device__ float g_bias1[(size_t)NSITE * Hv];
__device__ __half g_W1f[KA * Hv];
__device__ __half g_W2f[Hv * Hv];
__device__ __half g_W3f[Hv * Hv];

__device__ __forceinline__ float geluf(float x) {
    return 0.5f * x * (1.0f + erff(x * 0.7071067811865476f));
}
__device__ __forceinline__ unsigned pack2h(float a, float b) {
    __half2 v = __floats2half2_rn(a, b);
    return *(unsigned*)&v;
}

// ------------------------- small prep kernels -----------------------------
__global__ void wprep_kernel(const float* __restrict__ W1,
                             const float* __restrict__ W2,
                             const float* __restrict__ W3) {
    int idx = blockIdx.x * 256 + threadIdx.x;
    if (idx < KA * Hv) {
        int j = idx / Hv, c = idx % Hv;
        float v = (j < 456) ? W1[(Hv + j) * Hv + c] : 0.0f;
        g_W1f[idx] = __float2half_rn(v);
    } else if (idx < KA * Hv + Hv * Hv) {
        int i2 = idx - KA * Hv;
        g_W2f[i2] = __float2half_rn(W2[i2]);
    } else if (idx < KA * Hv + 2 * Hv * Hv) {
        int i3 = idx - KA * Hv - Hv * Hv;
        g_W3f[i3] = __float2half_rn(W3[i3]);
    }
}

// node-term bias: bias1[site][c] = b1[c] + sum_r hV[site,r]*W1[r,c]  (exact fp32)
__global__ __launch_bounds__(128) void bias1_kernel(const float* __restrict__ hV,
                                                    const float* __restrict__ W1,
                                                    const float* __restrict__ b1) {
    extern __shared__ float bsm[];
    float* sW = bsm;
    float* shv = bsm + 16384;
    int c = threadIdx.x;
    for (int i = c; i < 16384; i += 128) sW[i] = W1[i];
    __syncthreads();
    for (int site = blockIdx.x; site < NSITE; site += gridDim.x) {
        shv[c] = hV[(size_t)site * Hv + c];
        __syncthreads();
        float acc = b1[c];
        #pragma unroll 8
        for (int r = 0; r < Hv; r++) acc = fmaf(shv[r], sW[r * Hv + c], acc);
        g_bias1[(size_t)site * Hv + c] = acc;
        __syncthreads();
    }
}

__device__ __forceinline__ void make_frame(const float* __restrict__ x,
                                           float* __restrict__ R,
                                           float* __restrict__ t) {
    float Nx = x[0], Ny = x[1], Nz = x[2];
    float CAx = x[3], CAy = x[4], CAz = x[5];
    float Cx = x[6], Cy = x[7], Cz = x[8];
    float e0x = CAx - Nx, e0y = CAy - Ny, e0z = CAz - Nz;
    float inv = 1.0f / sqrtf(e0x * e0x + e0y * e0y + e0z * e0z + EPSv);
    e0x *= inv; e0y *= inv; e0z *= inv;
    float e1x = Cx - CAx, e1y = Cy - CAy, e1z = Cz - CAz;
    float d = e0x * e1x + e0y * e1y + e0z * e1z;
    e1x -= e0x * d; e1y -= e0y * d; e1z -= e0z * d;
    inv = 1.0f / sqrtf(e1x * e1x + e1y * e1y + e1z * e1z + EPSv);
    e1x *= inv; e1y *= inv; e1z *= inv;
    float e2x = e0y * e1z - e0z * e1y;
    float e2y = e0z * e1x - e0x * e1z;
    float e2z = e0x * e1y - e0y * e1x;
    R[0] = e0x; R[1] = e1x; R[2] = e2x;
    R[3] = e0y; R[4] = e1y; R[5] = e2y;
    R[6] = e0z; R[7] = e1z; R[8] = e2z;
    t[0] = CAx; t[1] = CAy; t[2] = CAz;
}

// ---------------------------------------------------------------------------
// geoFeat: 2 sites per block, 256 threads; shared Wp stage.
// ---------------------------------------------------------------------------
#define GH_HVP  0
#define GH_PLN  3870
#define GH_R    4590
#define GH_T    4860
#define GH_NPG  4950
#define GH_FEAT 5670
#define GH_SIZE 7830
#define GEOF_SMEM ((3072 + 2 * GH_SIZE) * 4)   // 74928 bytes

__global__ void __launch_bounds__(256) geoFeat_kernel(
    const float* __restrict__ hE,
    const float* __restrict__ Xn,
    const float* __restrict__ Wp,
    const float* __restrict__ bp)
{
    extern __shared__ float gs[];
    int tid = threadIdx.x;
    int hf = tid >> 7, t = tid & 127;
    int site = blockIdx.x * 2 + hf;

    float* WP = gs;
    float* base = gs + 3072 + hf * GH_SIZE;

    for (int i = tid; i < 3072; i += 256) WP[i] = Wp[i];
    for (int i = t; i < 30 * 128; i += 128) {
        int k = i >> 7, j = i & 127;
        base[GH_HVP + k * 129 + j] = hE[((size_t)(site * Kv + k)) * NINv + 256 + j];
    }
    if (t < Kv) make_frame(Xn + ((size_t)(site * Kv + t)) * 9,
                           base + GH_R + t * 9, base + GH_T + t * 3);
    __syncthreads();

    // p_ln[30][24]: 120 threads x 6 cols
    if (t < 120) {
        int k = t % 30, g = t / 30;
        float acc[6];
        #pragma unroll
        for (int j = 0; j < 6; j++) acc[j] = bp[g * 6 + j];
        const float* e = base + GH_HVP + k * 129;
        const float* wbase = WP + g * 6;
        #pragma unroll 4
        for (int i = 0; i < 128; i++) {
            float h = e[i];
            const float* wr = wbase + i * 24;
            float2 w01 = *(const float2*)(wr);
            float2 w23 = *(const float2*)(wr + 2);
            float2 w45 = *(const float2*)(wr + 4);
            acc[0] = fmaf(h, w01.x, acc[0]);
            acc[1] = fmaf(h, w01.y, acc[1]);
            acc[2] = fmaf(h, w23.x, acc[2]);
            acc[3] = fmaf(h, w23.y, acc[3]);
            acc[4] = fmaf(h, w45.x, acc[4]);
            acc[5] = fmaf(h, w45.y, acc[5]);
        }
        #pragma unroll
        for (int j = 0; j < 6; j++) base[GH_PLN + k * 24 + g * 6 + j] = acc[j];
    }
    __syncthreads();

    // npg: (k,n) parallel, 240 work items over 128 threads
    for (int p = t; p < 240; p += 128) {
        int k = p / 8, n = p % 8;
        const float* R = base + GH_R + k * 9;
        const float* tt = base + GH_T + k * 3;
        const float* pl = base + GH_PLN + k * 24 + n * 3;
        #pragma unroll
        for (int i = 0; i < 3; i++)
            base[GH_NPG + k * 24 + n * 3 + i] =
                tt[i] + R[i * 3] * pl[0] + R[i * 3 + 1] * pl[1] + R[i * 3 + 2] * pl[2];
    }
    __syncthreads();

    // feats: (k,n) parallel
    for (int p = t; p < 240; p += 128) {
        int k = p / 8, n = p % 8;
        float* f = base + GH_FEAT + k * 72;
        const float* pl0 = base + GH_PLN + n * 3;
        const float* pg  = base + GH_NPG + n * 3;
        const float* R0  = base + GH_R;
        const float* t0  = base + GH_T;
        const float* ng  = base + GH_NPG + k * 24 + n * 3;
        float p0 = pl0[0], p1 = pl0[1], p2 = pl0[2];
        f[n * 3] = p0; f[n * 3 + 1] = p1; f[n * 3 + 2] = p2;
        f[24 + n] = sqrtf(p0 * p0 + p1 * p1 + p2 * p2 + EPSv);
        float d0 = ng[0] - t0[0], d1 = ng[1] - t0[1], d2 = ng[2] - t0[2];
        float n0 = R0[0] * d0 + R0[3] * d1 + R0[6] * d2;
        float n1 = R0[1] * d0 + R0[4] * d1 + R0[7] * d2;
        float n2 = R0[2] * d0 + R0[5] * d1 + R0[8] * d2;
        f[32 + n * 3] = n0; f[32 + n * 3 + 1] = n1; f[32 + n * 3 + 2] = n2;
        f[56 + n] = sqrtf(n0 * n0 + n1 * n1 + n2 * n2 + EPSv);
        float gx = pg[0] - ng[0], gy = pg[1] - ng[1], gz = pg[2] - ng[2];
        f[64 + n] = sqrtf(gx * gx + gy * gy + gz * gz + EPSv);
    }
    __syncthreads();

    for (int i = t; i < 30 * 96; i += 128) {
        int k = i / 96, col = i - k * 96;
        float v = (col < 72) ? base[GH_FEAT + k * 72 + col] : 0.0f;
        g_feat[((size_t)(site * 32 + k)) * 96 + col] = v;
    }
}

// ---------------------------------------------------------------------------
// Fused GEMM, single-pass fp16: A fp16, weights fp16, fp32 accum.
// C3 = gelu(gelu(A@W1+bias1)@W2+b2)@W3 + b3.
// 256 thr, M-tile 128 = 4 sites x 32 padded edges.
// smem: Abuf 2x10240 [0,20480) | Wst 2x8704 [20480,37888)
//       W2/W3 (34816) reuse [0,34816) after phase 1 / phase 2.
// ---------------------------------------------------------------------------
#define ABUF(i)  ((i) * 10240)
#define WST(i)   (20480 + (i) * 8704)
#define OFF_W    0
#define GEMM_SMEM 37888

__device__ __forceinline__ void cpasync16(unsigned dst, const void* src) {
    asm volatile("cp.async.cg.shared.global [%0], [%1], 16;\n" :: "r"(dst), "l"(src));
}
__device__ __forceinline__ void ldm_x4(unsigned* r, unsigned addr) {
    asm volatile("ldmatrix.sync.aligned.m8n8.x4.shared.b16 {%0,%1,%2,%3}, [%4];"
        : "=r"(r[0]), "=r"(r[1]), "=r"(r[2]), "=r"(r[3]) : "r"(addr));
}
__device__ __forceinline__ void ldm_x4_t(unsigned* r, unsigned addr) {
    asm volatile("ldmatrix.sync.aligned.m8n8.x4.trans.shared.b16 {%0,%1,%2,%3}, [%4];"
        : "=r"(r[0]), "=r"(r[1]), "=r"(r[2]), "=r"(r[3]) : "r"(addr));
}
__device__ __forceinline__ void mma_f16(float* d, const unsigned* a, unsigned b0, unsigned b1) {
    asm volatile("mma.sync.aligned.m16n8k16.row.col.f32.f16.f16.f32 "
        "{%0,%1,%2,%3}, {%4,%5,%6,%7}, {%8,%9}, {%0,%1,%2,%3};"
        : "+f"(d[0]), "+f"(d[1]), "+f"(d[2]), "+f"(d[3])
        : "r"(a[0]), "r"(a[1]), "r"(a[2]), "r"(a[3]), "r"(b0), "r"(b1));
}
__device__ __forceinline__ void sts128(unsigned addr, const unsigned* v) {
    asm volatile("st.shared.v4.b32 [%0], {%1,%2,%3,%4};"
        :: "r"(addr), "r"(v[0]), "r"(v[1]), "r"(v[2]), "r"(v[3]));
}

// W1 k-chunk loader: 32 rows of W1f into WST(st) (stride 136 halves)
__device__ __forceinline__ void wload_chunk(unsigned sbase, int st,
                                            const __half* __restrict__ W1f,
                                            int kc, int tid) {
    unsigned wst = sbase + WST(st);
    #pragma unroll
    for (int i = 0; i < 2; i++) {
        int tt = tid + i * 256;
        int rb = tt >> 4, sg = tt & 15;
        cpasync16(wst + (rb * 136 + sg * 8) * 2, W1f + (size_t)(kc + rb) * Hv + sg * 8);
    }
    asm volatile("cp.async.commit_group;\n" ::);
}

// Full 128x128 fp16 weight into [off, off+34816)
__device__ __forceinline__ void load_weight(unsigned sbase, unsigned off,
                                            const __half* __restrict__ src, int tid) {
    #pragma unroll
    for (int i = 0; i < 8; i++) {
        int idx = tid + i * 256;
        int r = idx >> 4, s = idx & 15;
        cpasync16(sbase + off + (r * 136 + s * 8) * 2, src + (size_t)r * Hv + s * 8);
    }
}

__global__ __launch_bounds__(256, 2) void fusedgemm_kernel(
    const float* __restrict__ hE, const float* __restrict__ feat,
    const __half* __restrict__ W1f, const __half* __restrict__ W2f,
    const __half* __restrict__ W3f,
    const float* __restrict__ bias1,
    const float* __restrict__ b2, const float* __restrict__ b3,
    float* __restrict__ C3)
{
    extern __shared__ __align__(16) unsigned char gsm[];
    unsigned sbase = (unsigned)__cvta_generic_to_shared(gsm);

    int tid = threadIdx.x;
    int lane = tid & 31, w = tid >> 5;
    int rowBase = blockIdx.x * 128;

    // A loader identity: thread covers row arow, 16 cols at half16*16
    int arow = tid >> 1, half16 = tid & 1;
    int gr = rowBase + arow;
    int asite = gr >> 5;
    int ak = gr & 31; if (ak > 29) ak = 29;
    const float* hE_row = hE + ((size_t)(asite * Kv + ak)) * NINv + half16 * 16;
    const float* ft_row = feat + ((size_t)(asite * 32 + ak)) * 96 + half16 * 16;

    float4 f0, f1, f2, f3;
    #define LDA(cc) do { \
        const float4* s4 = (const float4*)(((cc) < 12) ? (hE_row + (cc) * 32) \
                                                       : (ft_row + ((cc) - 12) * 32)); \
        f0 = s4[0]; f1 = s4[1]; f2 = s4[2]; f3 = s4[3]; \
    } while (0)

    #define CVTSTS(buf) do { \
        unsigned uh[8]; \
        uh[0] = pack2h(f0.x, f0.y); uh[1] = pack2h(f0.z, f0.w); \
        uh[2] = pack2h(f1.x, f1.y); uh[3] = pack2h(f1.z, f1.w); \
        uh[4] = pack2h(f2.x, f2.y); uh[5] = pack2h(f2.z, f2.w); \
        uh[6] = pack2h(f3.x, f3.y); uh[7] = pack2h(f3.z, f3.w); \
        unsigned ab = sbase + ABUF(buf) + (unsigned)((arow * 40 + half16 * 16) * 2); \
        sts128(ab, uh); sts128(ab + 16, uh + 4); \
    } while (0)

    float acc[16][4];
    #pragma unroll
    for (int t = 0; t < 16; t++)
        #pragma unroll
        for (int q = 0; q < 4; q++) acc[t][q] = 0.0f;

    // prologue
    wload_chunk(sbase, 0, W1f, 0, tid);
    wload_chunk(sbase, 1, W1f, 32, tid);
    LDA(0);
    CVTSTS(0);

    // -------- phase 1: A @ W1, K=480, single-pass fp16 --------
    for (int c = 0; c < NCH; c++) {
        if (c + 1 < NCH) { asm volatile("cp.async.wait_group 1;\n" ::); }
        else             { asm volatile("cp.async.wait_group 0;\n" ::); }
        __syncthreads();

        if (c + 1 < NCH) LDA(c + 1);

        unsigned abuf = sbase + ABUF(c & 1);
        unsigned wst  = sbase + WST(c & 1);
        #pragma unroll
        for (int kk = 0; kk < 32; kk += 16) {
            unsigned aH[4];
            {
                int row = w * 16 + (lane & 15);
                unsigned off = (unsigned)((row * 40 + kk + ((lane >> 4) << 3)) * 2);
                ldm_x4(aH, abuf + off);
            }
            #pragma unroll
            for (int nb = 0; nb < 8; nb++) {
                unsigned offb = (unsigned)(((kk + (lane & 15)) * 136 + nb * 16 + ((lane >> 4) << 3)) * 2);
                unsigned bh[4];
                ldm_x4_t(bh, wst + offb);
                mma_f16(acc[2 * nb],     aH, bh[0], bh[1]);
                mma_f16(acc[2 * nb + 1], aH, bh[2], bh[3]);
            }
        }

        if (c + 1 < NCH) CVTSTS((c + 1) & 1);
        __syncthreads();
        if (c + 2 < NCH) wload_chunk(sbase, c & 1, W1f, (c + 2) * 32, tid);
    }

    // W2 into [0, 34816) — stage buffers dead
    load_weight(sbase, OFF_W, W2f, tid);
    asm volatile("cp.async.commit_group;\n" ::);

    // phase-1 epilogue: + bias1(site), gelu, pack fp16 A fragments (regs only)
    int r0 = w * 16 + (lane >> 2);
    int r1 = r0 + 8;
    const float* bs0 = bias1 + (size_t)((rowBase + r0) >> 5) * Hv;
    const float* bs1 = bias1 + (size_t)((rowBase + r1) >> 5) * Hv;

    unsigned a_h[16][2];
    #pragma unroll
    for (int t = 0; t < 16; t++) {
        int col = t * 8 + ((lane & 3) << 1);
        float2 c0 = *(const float2*)(bs0 + col);
        float2 c1 = *(const float2*)(bs1 + col);
        float v00 = geluf(acc[t][0] + c0.x);
        float v01 = geluf(acc[t][1] + c0.y);
        float v10 = geluf(acc[t][2] + c1.x);
        float v11 = geluf(acc[t][3] + c1.y);
        a_h[t][0] = pack2h(v00, v01);
        a_h[t][1] = pack2h(v10, v11);
        acc[t][0] = 0.0f; acc[t][1] = 0.0f; acc[t][2] = 0.0f; acc[t][3] = 0.0f;
    }
    asm volatile("cp.async.wait_group 0;\n" ::);
    __syncthreads();

    // -------- phase 2: C1 @ W2 --------
    #pragma unroll
    for (int q = 0; q < 8; q++) {
        unsigned aH[4] = { a_h[2 * q][0], a_h[2 * q][1], a_h[2 * q + 1][0], a_h[2 * q + 1][1] };
        #pragma unroll
        for (int nb = 0; nb < 8; nb++) {
            unsigned offb = (unsigned)(((q * 16 + (lane & 15)) * 136 + nb * 16 + ((lane >> 4) << 3)) * 2);
            unsigned bh[4];
            ldm_x4_t(bh, sbase + OFF_W + offb);
            mma_f16(acc[2 * nb],     aH, bh[0], bh[1]);
            mma_f16(acc[2 * nb + 1], aH, bh[2], bh[3]);
        }
    }
    __syncthreads();   // all warps done reading W2
    load_weight(sbase, OFF_W, W3f, tid);
    asm volatile("cp.async.commit_group;\n" ::);

    // phase-2 epilogue: + b2, gelu, pack
    #pragma unroll
    for (int t = 0; t < 16; t++) {
        int col = t * 8 + ((lane & 3) << 1);
        float2 bb = *(const float2*)(b2 + col);
        float v00 = geluf(acc[t][0] + bb.x);
        float v01 = geluf(acc[t][1] + bb.y);
        float v10 = geluf(acc[t][2] + bb.x);
        float v11 = geluf(acc[t][3] + bb.y);
        a_h[t][0] = pack2h(v00, v01);
        a_h[t][1] = pack2h(v10, v11);
        acc[t][0] = 0.0f; acc[t][1] = 0.0f; acc[t][2] = 0.0f; acc[t][3] = 0.0f;
    }
    asm volatile("cp.async.wait_group 0;\n" ::);
    __syncthreads();

    // -------- phase 3: C2 @ W3 --------
    #pragma unroll
    for (int q = 0; q < 8; q++) {
        unsigned aH[4] = { a_h[2 * q][0], a_h[2 * q][1], a_h[2 * q + 1][0], a_h[2 * q + 1][1] };
        #pragma unroll
        for (int nb = 0; nb < 8; nb++) {
            unsigned offb = (unsigned)(((q * 16 + (lane & 15)) * 136 + nb * 16 + ((lane >> 4) << 3)) * 2);
            unsigned bh[4];
            ldm_x4_t(bh, sbase + OFF_W + offb);
            mma_f16(acc[2 * nb],     aH, bh[0], bh[1]);
            mma_f16(acc[2 * nb + 1], aH, bh[2], bh[3]);
        }
    }

    // final epilogue: + b3, store fp32 C3
    #pragma unroll
    for (int t = 0; t < 16; t++) {
        int col = t * 8 + ((lane & 3) << 1);
        float2 bb = *(const float2*)(b3 + col);
        float2 v0; v0.x = acc[t][0] + bb.x; v0.y = acc[t][1] + bb.y;
        float2 v1; v1.x = acc[t][2] + bb.x; v1.y = acc[t][3] + bb.y;
        *(float2*)(C3 + (size_t)(rowBase + r0) * Hv + col) = v0;
        *(float2*)(C3 + (size_t)(rowBase + r1) * Hv + col) = v1;
    }
    #undef LDA
    #undef CVTSTS
}

// ---------------------------------------------------------------------------
// Final: masked mean + LN1 + FFN + LN2 + out. 8 sites/block, 256 threads.
// FFN hidden dim and j-sum each split 2-way across thread halves.
// ---------------------------------------------------------------------------
#define SPB 8
__global__ __launch_bounds__(256) void final_kernel(
    const float* __restrict__ hV, const float* __restrict__ maskV,
    const float* __restrict__ maskA,
    const float* __restrict__ Wi, const float* __restrict__ bi,
    const float* __restrict__ Wo, const float* __restrict__ bo,
    const float* __restrict__ g1, const float* __restrict__ be1,
    const float* __restrict__ g2, const float* __restrict__ be2,
    float* __restrict__ out)
{
    __shared__ float s_h[SPB][Hv];
    __shared__ float s_f[SPB][4 * Hv];
    __shared__ float s_dp[2][SPB][Hv];
    __shared__ float s_red[8];
    int tid = threadIdx.x;
    int c = tid & 127, hfi = tid >> 7;
    int base_site = blockIdx.x * SPB;

    // ---- masked mean + LN1 (first 128 threads active) ----
    for (int s = 0; s < SPB; s++) {
        if (hfi == 0) {
            int site = base_site + s;
            const float* c3 = g_C3 + (size_t)site * 32 * Hv + c;
            const float* ma = maskA + (size_t)site * Kv;
            float nm = 0.0f;
            #pragma unroll
            for (int k = 0; k < Kv; k++) nm += c3[k * Hv] * ma[k];
            nm *= (1.0f / (float)Kv);
            float xv = hV[(size_t)site * Hv + c] + nm;
            float sum = xv, sq = xv * xv;
            #pragma unroll
            for (int o = 16; o; o >>= 1) {
                sum += __shfl_xor_sync(0xffffffffu, sum, o);
                sq  += __shfl_xor_sync(0xffffffffu, sq, o);
            }
            if ((c & 31) == 0) { s_red[c >> 5] = sum; s_red[4 + (c >> 5)] = sq; }
            s_dp[0][s][c] = xv;   // stash xv
        }
        __syncthreads();
        if (hfi == 0) {
            float sum = s_red[0] + s_red[1] + s_red[2] + s_red[3];
            float sq  = s_red[4] + s_red[5] + s_red[6] + s_red[7];
            float mean = sum * (1.0f / Hv);
            float var  = sq * (1.0f / Hv) - mean * mean;
            float xv = s_dp[0][s][c];
            s_h[s][c] = (xv - mean) * rsqrtf(var + 1e-5f) * g1[c] + be1[c];
        }
        __syncthreads();
    }

    // ---- FFN layer 1: 256 threads x 2 hidden cols ----
    float hi2[SPB][2];
    #pragma unroll
    for (int s = 0; s < SPB; s++) {
        hi2[s][0] = bi[tid];
        hi2[s][1] = bi[tid + 256];
    }
    for (int r = 0; r < Hv; r++) {
        const float* wr = Wi + (size_t)r * 512;
        float w0 = wr[tid], w1 = wr[tid + 256];
        #pragma unroll
        for (int s = 0; s < SPB; s++) {
            float hv = s_h[s][r];
            hi2[s][0] = fmaf(hv, w0, hi2[s][0]);
            hi2[s][1] = fmaf(hv, w1, hi2[s][1]);
        }
    }
    #pragma unroll
    for (int s = 0; s < SPB; s++) {
        s_f[s][tid]       = geluf(hi2[s][0]);
        s_f[s][tid + 256] = geluf(hi2[s][1]);
    }
    __syncthreads();

    // ---- FFN layer 2: j-split 2-way ----
    float dp[SPB];
    #pragma unroll
    for (int s = 0; s < SPB; s++) dp[s] = 0.0f;
    int j0 = hfi * 256;
    for (int jj = 0; jj < 256; jj++) {
        int j = j0 + jj;
        float wv = Wo[(size_t)j * Hv + c];
        #pragma unroll
        for (int s = 0; s < SPB; s++) dp[s] = fmaf(s_f[s][j], wv, dp[s]);
    }
    #pragma unroll
    for (int s = 0; s < SPB; s++) s_dp[hfi][s][c] = dp[s];
    __syncthreads();

    // ---- LN2 + output (first 128 threads) ----
    for (int s = 0; s < SPB; s++) {
        float x2 = 0.0f;
        if (hfi == 0) {
            x2 = s_h[s][c] + bo[c] + s_dp[0][s][c] + s_dp[1][s][c];
            float sum = x2, sq = x2 * x2;
            #pragma unroll
            for (int o = 16; o; o >>= 1) {
                sum += __shfl_xor_sync(0xffffffffu, sum, o);
                sq  += __shfl_xor_sync(0xffffffffu, sq, o);
            }
            if ((c & 31) == 0) { s_red[c >> 5] = sum; s_red[4 + (c >> 5)] = sq; }
        }
        __syncthreads();
        if (hfi == 0) {
            int site = base_site + s;
            float sum = s_red[0] + s_red[1] + s_red[2] + s_red[3];
            float sq  = s_red[4] + s_red[5] + s_red[6] + s_red[7];
            float mean = sum * (1.0f / Hv);
            float var  = sq * (1.0f / Hv) - mean * mean;
            float h2 = (x2 - mean) * rsqrtf(var + 1e-5f) * g2[c] + be2[c];
            out[(size_t)site * Hv + c] = maskV[site] * h2;
        }
        __syncthreads();
    }
}

// ---------------------------------------------------------------------------

extern "C" void kernel_launch(void* const* d_in, const int* in_sizes, int n_in,
                              void* d_out, int out_size) {
    const float* hV    = (const float*)d_in[0];
    const float* hE    = (const float*)d_in[1];
    const float* Xn    = (const float*)d_in[3];
    const float* maskV = (const float*)d_in[4];
    const float* maskA = (const float*)d_in[5];
    const float* Wp    = (const float*)d_in[6];
    const float* bp    = (const float*)d_in[7];
    const float* W1    = (const float*)d_in[8];
    const float* b1    = (const float*)d_in[9];
    const float* W2    = (const float*)d_in[10];
    const float* b2    = (const float*)d_in[11];
    const float* W3    = (const float*)d_in[12];
    const float* b3    = (const float*)d_in[13];
    const float* Wi    = (const float*)d_in[14];
    const float* bi    = (const float*)d_in[15];
    const float* Wo    = (const float*)d_in[16];
    const float* bo    = (const float*)d_in[17];
    const float* g1    = (const float*)d_in[18];
    const float* be1   = (const float*)d_in[19];
    const float* g2    = (const float*)d_in[20];
    const float* be2   = (const float*)d_in[21];
    float* out = (float*)d_out;

    cudaFuncSetAttribute(fusedgemm_kernel, cudaFuncAttributeMaxDynamicSharedMemorySize, GEMM_SMEM);
    cudaFuncSetAttribute(bias1_kernel, cudaFuncAttributeMaxDynamicSharedMemorySize, 66048);
    cudaFuncSetAttribute(geoFeat_kernel, cudaFuncAttributeMaxDynamicSharedMemorySize, GEOF_SMEM);

    static void *pFeat = nullptr, *pC3, *pB1, *pW1f, *pW2f, *pW3f;
    if (!pFeat) {
        cudaGetSymbolAddress(&pFeat, g_feat);
        cudaGetSymbolAddress(&pC3, g_C3);   cudaGetSymbolAddress(&pB1, g_bias1);
        cudaGetSymbolAddress(&pW1f, g_W1f);
        cudaGetSymbolAddress(&pW2f, g_W2f);
        cudaGetSymbolAddress(&pW3f, g_W3f);
    }

    wprep_kernel<<<(KA * Hv + 2 * Hv * Hv + 255) / 256, 256>>>(W1, W2, W3);
    bias1_kernel<<<512, 128, 66048>>>(hV, W1, b1);
    geoFeat_kernel<<<NSITE / 2, 256, GEOF_SMEM>>>(hE, Xn, Wp, bp);

    fusedgemm_kernel<<<MPAD / 128, 256, GEMM_SMEM>>>(
        hE, (const float*)pFeat,
        (const __half*)pW1f, (const __half*)pW2f, (const __half*)pW3f,
        (const float*)pB1, b2, b3, (float*)pC3);

    final_kernel<<<NSITE / SPB, 256>>>(hV, maskV, maskA, Wi, bi, Wo, bo,
                                       g1, be1, g2, be2, out);
}

// round 12
// speedup vs baseline: 1.2209x; 1.0880x over previous
#include <cuda_runtime.h>
#include <cuda_fp16.h>
#include <math.h>

#define Bv 8
#define Lv 512
#define Kv 30
#define Hv 128
#define NINv 384
#define EPSv 1e-8f

#define NSITE (Bv * Lv)          // 4096
#define MPAD (NSITE * 32)        // 131072 padded rows (32 edges/site)
#define KA 480
#define NCH 15                   // 480/32 k-chunks

// ------------------------- global scratch (static, no allocs) -------------
__device__ float g_feat[(size_t)MPAD * 96];
__device__ float g_nodem[(size_t)NSITE * Hv];   // fused masked mean output
__device__ float g_bias1[(size_t)NSITE * Hv];
__device__ __half g_W1f[KA * Hv];
__device__ __half g_W2f[Hv * Hv];
__device__ __half g_W3f[Hv * Hv];

__device__ __forceinline__ float geluf(float x) {
    return 0.5f * x * (1.0f + erff(x * 0.7071067811865476f));
}
__device__ __forceinline__ unsigned pack2h(float a, float b) {
    __half2 v = __floats2half2_rn(a, b);
    return *(unsigned*)&v;
}

// ------------------------- small prep kernels -----------------------------
__global__ void wprep_kernel(const float* __restrict__ W1,
                             const float* __restrict__ W2,
                             const float* __restrict__ W3) {
    int idx = blockIdx.x * 256 + threadIdx.x;
    if (idx < KA * Hv) {
        int j = idx / Hv, c = idx % Hv;
        float v = (j < 456) ? W1[(Hv + j) * Hv + c] : 0.0f;
        g_W1f[idx] = __float2half_rn(v);
    } else if (idx < KA * Hv + Hv * Hv) {
        int i2 = idx - KA * Hv;
        g_W2f[i2] = __float2half_rn(W2[i2]);
    } else if (idx < KA * Hv + 2 * Hv * Hv) {
        int i3 = idx - KA * Hv - Hv * Hv;
        g_W3f[i3] = __float2half_rn(W3[i3]);
    }
}

__global__ __launch_bounds__(128) void bias1_kernel(const float* __restrict__ hV,
                                                    const float* __restrict__ W1,
                                                    const float* __restrict__ b1) {
    extern __shared__ float bsm[];
    float* sW = bsm;
    float* shv = bsm + 16384;
    int c = threadIdx.x;
    for (int i = c; i < 16384; i += 128) sW[i] = W1[i];
    __syncthreads();
    for (int site = blockIdx.x; site < NSITE; site += gridDim.x) {
        shv[c] = hV[(size_t)site * Hv + c];
        __syncthreads();
        float acc = b1[c];
        #pragma unroll 8
        for (int r = 0; r < Hv; r++) acc = fmaf(shv[r], sW[r * Hv + c], acc);
        g_bias1[(size_t)site * Hv + c] = acc;
        __syncthreads();
    }
}

__device__ __forceinline__ void make_frame(const float* __restrict__ x,
                                           float* __restrict__ R,
                                           float* __restrict__ t) {
    float Nx = x[0], Ny = x[1], Nz = x[2];
    float CAx = x[3], CAy = x[4], CAz = x[5];
    float Cx = x[6], Cy = x[7], Cz = x[8];
    float e0x = CAx - Nx, e0y = CAy - Ny, e0z = CAz - Nz;
    float inv = 1.0f / sqrtf(e0x * e0x + e0y * e0y + e0z * e0z + EPSv);
    e0x *= inv; e0y *= inv; e0z *= inv;
    float e1x = Cx - CAx, e1y = Cy - CAy, e1z = Cz - CAz;
    float d = e0x * e1x + e0y * e1y + e0z * e1z;
    e1x -= e0x * d; e1y -= e0y * d; e1z -= e0z * d;
    inv = 1.0f / sqrtf(e1x * e1x + e1y * e1y + e1z * e1z + EPSv);
    e1x *= inv; e1y *= inv; e1z *= inv;
    float e2x = e0y * e1z - e0z * e1y;
    float e2y = e0z * e1x - e0x * e1z;
    float e2z = e0x * e1y - e0y * e1x;
    R[0] = e0x; R[1] = e1x; R[2] = e2x;
    R[3] = e0y; R[4] = e1y; R[5] = e2y;
    R[6] = e0z; R[7] = e1z; R[8] = e2z;
    t[0] = CAx; t[1] = CAy; t[2] = CAz;
}

// ---------------------------------------------------------------------------
// geoFeat: 2 sites per block, 256 threads (unchanged from R11)
// ---------------------------------------------------------------------------
#define GH_HVP  0
#define GH_PLN  3870
#define GH_R    4590
#define GH_T    4860
#define GH_NPG  4950
#define GH_FEAT 5670
#define GH_SIZE 7830
#define GEOF_SMEM ((3072 + 2 * GH_SIZE) * 4)

__global__ void __launch_bounds__(256) geoFeat_kernel(
    const float* __restrict__ hE, const float* __restrict__ Xn,
    const float* __restrict__ Wp, const float* __restrict__ bp)
{
    extern __shared__ float gs[];
    int tid = threadIdx.x;
    int hf = tid >> 7, t = tid & 127;
    int site = blockIdx.x * 2 + hf;
    float* WP = gs;
    float* base = gs + 3072 + hf * GH_SIZE;

    for (int i = tid; i < 3072; i += 256) WP[i] = Wp[i];
    for (int i = t; i < 30 * 128; i += 128) {
        int k = i >> 7, j = i & 127;
        base[GH_HVP + k * 129 + j] = hE[((size_t)(site * Kv + k)) * NINv + 256 + j];
    }
    if (t < Kv) make_frame(Xn + ((size_t)(site * Kv + t)) * 9,
                           base + GH_R + t * 9, base + GH_T + t * 3);
    __syncthreads();

    if (t < 120) {
        int k = t % 30, g = t / 30;
        float acc[6];
        #pragma unroll
        for (int j = 0; j < 6; j++) acc[j] = bp[g * 6 + j];
        const float* e = base + GH_HVP + k * 129;
        const float* wbase = WP + g * 6;
        #pragma unroll 4
        for (int i = 0; i < 128; i++) {
            float h = e[i];
            const float* wr = wbase + i * 24;
            float2 w01 = *(const float2*)(wr);
            float2 w23 = *(const float2*)(wr + 2);
            float2 w45 = *(const float2*)(wr + 4);
            acc[0] = fmaf(h, w01.x, acc[0]);
            acc[1] = fmaf(h, w01.y, acc[1]);
            acc[2] = fmaf(h, w23.x, acc[2]);
            acc[3] = fmaf(h, w23.y, acc[3]);
            acc[4] = fmaf(h, w45.x, acc[4]);
            acc[5] = fmaf(h, w45.y, acc[5]);
        }
        #pragma unroll
        for (int j = 0; j < 6; j++) base[GH_PLN + k * 24 + g * 6 + j] = acc[j];
    }
    __syncthreads();

    for (int p = t; p < 240; p += 128) {
        int k = p / 8, n = p % 8;
        const float* R = base + GH_R + k * 9;
        const float* tt = base + GH_T + k * 3;
        const float* pl = base + GH_PLN + k * 24 + n * 3;
        #pragma unroll
        for (int i = 0; i < 3; i++)
            base[GH_NPG + k * 24 + n * 3 + i] =
                tt[i] + R[i * 3] * pl[0] + R[i * 3 + 1] * pl[1] + R[i * 3 + 2] * pl[2];
    }
    __syncthreads();

    for (int p = t; p < 240; p += 128) {
        int k = p / 8, n = p % 8;
        float* f = base + GH_FEAT + k * 72;
        const float* pl0 = base + GH_PLN + n * 3;
        const float* pg  = base + GH_NPG + n * 3;
        const float* R0  = base + GH_R;
        const float* t0  = base + GH_T;
        const float* ng  = base + GH_NPG + k * 24 + n * 3;
        float p0 = pl0[0], p1 = pl0[1], p2 = pl0[2];
        f[n * 3] = p0; f[n * 3 + 1] = p1; f[n * 3 + 2] = p2;
        f[24 + n] = sqrtf(p0 * p0 + p1 * p1 + p2 * p2 + EPSv);
        float d0 = ng[0] - t0[0], d1 = ng[1] - t0[1], d2 = ng[2] - t0[2];
        float n0 = R0[0] * d0 + R0[3] * d1 + R0[6] * d2;
        float n1 = R0[1] * d0 + R0[4] * d1 + R0[7] * d2;
        float n2 = R0[2] * d0 + R0[5] * d1 + R0[8] * d2;
        f[32 + n * 3] = n0; f[32 + n * 3 + 1] = n1; f[32 + n * 3 + 2] = n2;
        f[56 + n] = sqrtf(n0 * n0 + n1 * n1 + n2 * n2 + EPSv);
        float gx = pg[0] - ng[0], gy = pg[1] - ng[1], gz = pg[2] - ng[2];
        f[64 + n] = sqrtf(gx * gx + gy * gy + gz * gz + EPSv);
    }
    __syncthreads();

    for (int i = t; i < 30 * 96; i += 128) {
        int k = i / 96, col = i - k * 96;
        float v = (col < 72) ? base[GH_FEAT + k * 72 + col] : 0.0f;
        g_feat[((size_t)(site * 32 + k)) * 96 + col] = v;
    }
}

// ---------------------------------------------------------------------------
// Fused GEMM + masked mean. 4x2 warp split: warp (wm,wn) owns 32 rows x 64 cols;
// warp wm's 32 rows = one site. Phases 2/3 exchange activations via smem C-tile.
// Output: node_m[site][128] only (no C3).
// smem: phase1 Abuf 2x10240 [0,20480) | Wst 2x8704 [20480,37888)
//       phase2/3: C-tile [0,34816) | W2/W3 [34816,69632)
// ---------------------------------------------------------------------------
#define ABUF(i)  ((i) * 10240)
#define WST(i)   (20480 + (i) * 8704)
#define CT       0
#define OFF_W2   34816
#define GEMM_SMEM 69632

__device__ __forceinline__ void cpasync16(unsigned dst, const void* src) {
    asm volatile("cp.async.cg.shared.global [%0], [%1], 16;\n" :: "r"(dst), "l"(src));
}
__device__ __forceinline__ void ldm_x4(unsigned* r, unsigned addr) {
    asm volatile("ldmatrix.sync.aligned.m8n8.x4.shared.b16 {%0,%1,%2,%3}, [%4];"
        : "=r"(r[0]), "=r"(r[1]), "=r"(r[2]), "=r"(r[3]) : "r"(addr));
}
__device__ __forceinline__ void ldm_x4_t(unsigned* r, unsigned addr) {
    asm volatile("ldmatrix.sync.aligned.m8n8.x4.trans.shared.b16 {%0,%1,%2,%3}, [%4];"
        : "=r"(r[0]), "=r"(r[1]), "=r"(r[2]), "=r"(r[3]) : "r"(addr));
}
__device__ __forceinline__ void mma_f16(float* d, const unsigned* a, unsigned b0, unsigned b1) {
    asm volatile("mma.sync.aligned.m16n8k16.row.col.f32.f16.f16.f32 "
        "{%0,%1,%2,%3}, {%4,%5,%6,%7}, {%8,%9}, {%0,%1,%2,%3};"
        : "+f"(d[0]), "+f"(d[1]), "+f"(d[2]), "+f"(d[3])
        : "r"(a[0]), "r"(a[1]), "r"(a[2]), "r"(a[3]), "r"(b0), "r"(b1));
}
__device__ __forceinline__ void sts128(unsigned addr, const unsigned* v) {
    asm volatile("st.shared.v4.b32 [%0], {%1,%2,%3,%4};"
        :: "r"(addr), "r"(v[0]), "r"(v[1]), "r"(v[2]), "r"(v[3]));
}

__device__ __forceinline__ void wload_chunk(unsigned sbase, int st,
                                            const __half* __restrict__ W1f,
                                            int kc, int tid) {
    unsigned wst = sbase + WST(st);
    #pragma unroll
    for (int i = 0; i < 2; i++) {
        int tt = tid + i * 256;
        int rb = tt >> 4, sg = tt & 15;
        cpasync16(wst + (rb * 136 + sg * 8) * 2, W1f + (size_t)(kc + rb) * Hv + sg * 8);
    }
    asm volatile("cp.async.commit_group;\n" ::);
}
__device__ __forceinline__ void load_weight(unsigned sbase, unsigned off,
                                            const __half* __restrict__ src, int tid) {
    #pragma unroll
    for (int i = 0; i < 8; i++) {
        int idx = tid + i * 256;
        int r = idx >> 4, s = idx & 15;
        cpasync16(sbase + off + (r * 136 + s * 8) * 2, src + (size_t)r * Hv + s * 8);
    }
}

__global__ __launch_bounds__(256, 2) void fusedgemm_kernel(
    const float* __restrict__ hE, const float* __restrict__ feat,
    const __half* __restrict__ W1f, const __half* __restrict__ W2f,
    const __half* __restrict__ W3f,
    const float* __restrict__ bias1,
    const float* __restrict__ b2, const float* __restrict__ b3,
    const float* __restrict__ maskA,
    float* __restrict__ nodem)
{
    extern __shared__ __align__(16) unsigned char gsm[];
    unsigned sbase = (unsigned)__cvta_generic_to_shared(gsm);

    int tid = threadIdx.x;
    int lane = tid & 31, w = tid >> 5;
    int wm = w >> 1, wn = w & 1;          // 4x2 warp grid
    int rowBase = blockIdx.x * 128;
    int site = blockIdx.x * 4 + wm;       // warp's 32 rows = this site

    // A loader identity (all 256 threads): row arow, 16 cols at half16*16
    int arow = tid >> 1, half16 = tid & 1;
    int gr = rowBase + arow;
    int asite = gr >> 5;
    int ak = gr & 31; if (ak > 29) ak = 29;
    const float* hE_row = hE + ((size_t)(asite * Kv + ak)) * NINv + half16 * 16;
    const float* ft_row = feat + ((size_t)(asite * 32 + ak)) * 96 + half16 * 16;

    float4 f0, f1, f2, f3;
    #define LDA(cc) do { \
        const float4* s4 = (const float4*)(((cc) < 12) ? (hE_row + (cc) * 32) \
                                                       : (ft_row + ((cc) - 12) * 32)); \
        f0 = s4[0]; f1 = s4[1]; f2 = s4[2]; f3 = s4[3]; \
    } while (0)
    #define CVTSTS(buf) do { \
        unsigned uh[8]; \
        uh[0] = pack2h(f0.x, f0.y); uh[1] = pack2h(f0.z, f0.w); \
        uh[2] = pack2h(f1.x, f1.y); uh[3] = pack2h(f1.z, f1.w); \
        uh[4] = pack2h(f2.x, f2.y); uh[5] = pack2h(f2.z, f2.w); \
        uh[6] = pack2h(f3.x, f3.y); uh[7] = pack2h(f3.z, f3.w); \
        unsigned ab = sbase + ABUF(buf) + (unsigned)((arow * 40 + half16 * 16) * 2); \
        sts128(ab, uh); sts128(ab + 16, uh + 4); \
    } while (0)

    float acc[2][8][4];
    #pragma unroll
    for (int ma = 0; ma < 2; ma++)
        #pragma unroll
        for (int na = 0; na < 8; na++)
            #pragma unroll
            for (int q = 0; q < 4; q++) acc[ma][na][q] = 0.0f;

    // prologue
    wload_chunk(sbase, 0, W1f, 0, tid);
    wload_chunk(sbase, 1, W1f, 32, tid);
    LDA(0);
    CVTSTS(0);

    // -------- phase 1: A @ W1, K=480 --------
    for (int c = 0; c < NCH; c++) {
        if (c + 1 < NCH) { asm volatile("cp.async.wait_group 1;\n" ::); }
        else             { asm volatile("cp.async.wait_group 0;\n" ::); }
        __syncthreads();

        if (c + 1 < NCH) LDA(c + 1);

        unsigned abuf = sbase + ABUF(c & 1);
        unsigned wst  = sbase + WST(c & 1);
        #pragma unroll
        for (int kk = 0; kk < 32; kk += 16) {
            unsigned aH[2][4];
            #pragma unroll
            for (int ma = 0; ma < 2; ma++) {
                int row = wm * 32 + ma * 16 + (lane & 15);
                unsigned off = (unsigned)((row * 40 + kk + ((lane >> 4) << 3)) * 2);
                ldm_x4(aH[ma], abuf + off);
            }
            #pragma unroll
            for (int nb = 0; nb < 4; nb++) {
                unsigned offb = (unsigned)(((kk + (lane & 15)) * 136 + wn * 64 + nb * 16 + ((lane >> 4) << 3)) * 2);
                unsigned bh[4];
                ldm_x4_t(bh, wst + offb);
                #pragma unroll
                for (int ma = 0; ma < 2; ma++) {
                    mma_f16(acc[ma][2 * nb],     aH[ma], bh[0], bh[1]);
                    mma_f16(acc[ma][2 * nb + 1], aH[ma], bh[2], bh[3]);
                }
            }
        }

        if (c + 1 < NCH) CVTSTS((c + 1) & 1);
        __syncthreads();
        if (c + 2 < NCH) wload_chunk(sbase, c & 1, W1f, (c + 2) * 32, tid);
    }

    // W2 into [34816, 69632)
    load_weight(sbase, OFF_W2, W2f, tid);
    asm volatile("cp.async.commit_group;\n" ::);

    // phase-1 epilogue: + bias1(site), gelu, store fp16 C1 tile to smem
    const float* bs = bias1 + (size_t)site * Hv;
    #pragma unroll
    for (int ma = 0; ma < 2; ma++)
        #pragma unroll
        for (int na = 0; na < 8; na++) {
            int row = wm * 32 + ma * 16 + (lane >> 2);
            int col = wn * 64 + na * 8 + ((lane & 3) << 1);
            float2 bb = *(const float2*)(bs + col);
            unsigned p0 = pack2h(geluf(acc[ma][na][0] + bb.x), geluf(acc[ma][na][1] + bb.y));
            unsigned p1 = pack2h(geluf(acc[ma][na][2] + bb.x), geluf(acc[ma][na][3] + bb.y));
            asm volatile("st.shared.b32 [%0], %1;" :: "r"(sbase + CT + (row * 136 + col) * 2), "r"(p0));
            asm volatile("st.shared.b32 [%0], %1;" :: "r"(sbase + CT + ((row + 8) * 136 + col) * 2), "r"(p1));
            acc[ma][na][0] = 0.0f; acc[ma][na][1] = 0.0f;
            acc[ma][na][2] = 0.0f; acc[ma][na][3] = 0.0f;
        }
    asm volatile("cp.async.wait_group 0;\n" ::);
    __syncthreads();

    // -------- phase 2: C1 @ W2 (A from smem C-tile) --------
    #pragma unroll
    for (int q = 0; q < 8; q++) {
        unsigned aH[2][4];
        #pragma unroll
        for (int ma = 0; ma < 2; ma++) {
            int row = wm * 32 + ma * 16 + (lane & 15);
            unsigned off = (unsigned)((row * 136 + q * 16 + ((lane >> 4) << 3)) * 2);
            ldm_x4(aH[ma], sbase + CT + off);
        }
        #pragma unroll
        for (int nb = 0; nb < 4; nb++) {
            unsigned offb = (unsigned)(((q * 16 + (lane & 15)) * 136 + wn * 64 + nb * 16 + ((lane >> 4) << 3)) * 2);
            unsigned bh[4];
            ldm_x4_t(bh, sbase + OFF_W2 + offb);
            #pragma unroll
            for (int ma = 0; ma < 2; ma++) {
                mma_f16(acc[ma][2 * nb],     aH[ma], bh[0], bh[1]);
                mma_f16(acc[ma][2 * nb + 1], aH[ma], bh[2], bh[3]);
            }
        }
    }
    __syncthreads();   // everyone done reading CT + W2
    load_weight(sbase, OFF_W2, W3f, tid);
    asm volatile("cp.async.commit_group;\n" ::);

    // phase-2 epilogue: + b2, gelu, store C2 tile
    #pragma unroll
    for (int ma = 0; ma < 2; ma++)
        #pragma unroll
        for (int na = 0; na < 8; na++) {
            int row = wm * 32 + ma * 16 + (lane >> 2);
            int col = wn * 64 + na * 8 + ((lane & 3) << 1);
            float2 bb = *(const float2*)(b2 + col);
            unsigned p0 = pack2h(geluf(acc[ma][na][0] + bb.x), geluf(acc[ma][na][1] + bb.y));
            unsigned p1 = pack2h(geluf(acc[ma][na][2] + bb.x), geluf(acc[ma][na][3] + bb.y));
            asm volatile("st.shared.b32 [%0], %1;" :: "r"(sbase + CT + (row * 136 + col) * 2), "r"(p0));
            asm volatile("st.shared.b32 [%0], %1;" :: "r"(sbase + CT + ((row + 8) * 136 + col) * 2), "r"(p1));
            acc[ma][na][0] = 0.0f; acc[ma][na][1] = 0.0f;
            acc[ma][na][2] = 0.0f; acc[ma][na][3] = 0.0f;
        }
    asm volatile("cp.async.wait_group 0;\n" ::);
    __syncthreads();

    // -------- phase 3: C2 @ W3 --------
    #pragma unroll
    for (int q = 0; q < 8; q++) {
        unsigned aH[2][4];
        #pragma unroll
        for (int ma = 0; ma < 2; ma++) {
            int row = wm * 32 + ma * 16 + (lane & 15);
            unsigned off = (unsigned)((row * 136 + q * 16 + ((lane >> 4) << 3)) * 2);
            ldm_x4(aH[ma], sbase + CT + off);
        }
        #pragma unroll
        for (int nb = 0; nb < 4; nb++) {
            unsigned offb = (unsigned)(((q * 16 + (lane & 15)) * 136 + wn * 64 + nb * 16 + ((lane >> 4) << 3)) * 2);
            unsigned bh[4];
            ldm_x4_t(bh, sbase + OFF_W2 + offb);
            #pragma unroll
            for (int ma = 0; ma < 2; ma++) {
                mma_f16(acc[ma][2 * nb],     aH[ma], bh[0], bh[1]);
                mma_f16(acc[ma][2 * nb + 1], aH[ma], bh[2], bh[3]);
            }
        }
    }

    // -------- fused masked-mean epilogue: node_m[site][col] --------
    // thread holds rows rk = ma*16 + (lane>>2) + {0,8} within the site.
    {
        const float* mrow = maskA + (size_t)site * Kv;
        int gq = lane >> 2;
        float wgt[2][2];
        #pragma unroll
        for (int ma = 0; ma < 2; ma++)
            #pragma unroll
            for (int h = 0; h < 2; h++) {
                int rk = ma * 16 + gq + h * 8;
                wgt[ma][h] = (rk < Kv) ? mrow[rk] : 0.0f;
            }
        float colsum[16];
        #pragma unroll
        for (int na = 0; na < 8; na++) {
            int col = wn * 64 + na * 8 + ((lane & 3) << 1);
            float2 bb = *(const float2*)(b3 + col);
            float s0 = 0.0f, s1 = 0.0f;
            #pragma unroll
            for (int ma = 0; ma < 2; ma++) {
                s0 += wgt[ma][0] * (acc[ma][na][0] + bb.x) + wgt[ma][1] * (acc[ma][na][2] + bb.x);
                s1 += wgt[ma][0] * (acc[ma][na][1] + bb.y) + wgt[ma][1] * (acc[ma][na][3] + bb.y);
            }
            colsum[2 * na] = s0;
            colsum[2 * na + 1] = s1;
        }
        #pragma unroll
        for (int j = 0; j < 16; j++) {
            float s = colsum[j];
            s += __shfl_xor_sync(0xffffffffu, s, 4);
            s += __shfl_xor_sync(0xffffffffu, s, 8);
            s += __shfl_xor_sync(0xffffffffu, s, 16);
            colsum[j] = s;
        }
        if (lane < 4) {
            #pragma unroll
            for (int na = 0; na < 8; na++) {
                int col = wn * 64 + na * 8 + lane * 2;
                float2 v;
                v.x = colsum[2 * na] * (1.0f / (float)Kv);
                v.y = colsum[2 * na + 1] * (1.0f / (float)Kv);
                *(float2*)(nodem + (size_t)site * Hv + col) = v;
            }
        }
    }
}

// ---------------------------------------------------------------------------
// Final: node_m read + LN1 + FFN + LN2 + out. 8 sites/block, 256 threads.
// ---------------------------------------------------------------------------
#define SPB 8
__global__ __launch_bounds__(256) void final_kernel(
    const float* __restrict__ hV, const float* __restrict__ maskV,
    const float* __restrict__ Wi, const float* __restrict__ bi,
    const float* __restrict__ Wo, const float* __restrict__ bo,
    const float* __restrict__ g1, const float* __restrict__ be1,
    const float* __restrict__ g2, const float* __restrict__ be2,
    float* __restrict__ out)
{
    __shared__ float s_h[SPB][Hv];
    __shared__ float s_f[SPB][4 * Hv];
    __shared__ float s_dp[2][SPB][Hv];
    __shared__ float s_red[8];
    int tid = threadIdx.x;
    int c = tid & 127, hfi = tid >> 7;
    int base_site = blockIdx.x * SPB;

    for (int s = 0; s < SPB; s++) {
        if (hfi == 0) {
            int site = base_site + s;
            float xv = hV[(size_t)site * Hv + c] + g_nodem[(size_t)site * Hv + c];
            float sum = xv, sq = xv * xv;
            #pragma unroll
            for (int o = 16; o; o >>= 1) {
                sum += __shfl_xor_sync(0xffffffffu, sum, o);
                sq  += __shfl_xor_sync(0xffffffffu, sq, o);
            }
            if ((c & 31) == 0) { s_red[c >> 5] = sum; s_red[4 + (c >> 5)] = sq; }
            s_dp[0][s][c] = xv;
        }
        __syncthreads();
        if (hfi == 0) {
            float sum = s_red[0] + s_red[1] + s_red[2] + s_red[3];
            float sq  = s_red[4] + s_red[5] + s_red[6] + s_red[7];
            float mean = sum * (1.0f / Hv);
            float var  = sq * (1.0f / Hv) - mean * mean;
            float xv = s_dp[0][s][c];
            s_h[s][c] = (xv - mean) * rsqrtf(var + 1e-5f) * g1[c] + be1[c];
        }
        __syncthreads();
    }

    float hi2[SPB][2];
    #pragma unroll
    for (int s = 0; s < SPB; s++) {
        hi2[s][0] = bi[tid];
        hi2[s][1] = bi[tid + 256];
    }
    for (int r = 0; r < Hv; r++) {
        const float* wr = Wi + (size_t)r * 512;
        float w0 = wr[tid], w1 = wr[tid + 256];
        #pragma unroll
        for (int s = 0; s < SPB; s++) {
            float hv = s_h[s][r];
            hi2[s][0] = fmaf(hv, w0, hi2[s][0]);
            hi2[s][1] = fmaf(hv, w1, hi2[s][1]);
        }
    }
    #pragma unroll
    for (int s = 0; s < SPB; s++) {
        s_f[s][tid]       = geluf(hi2[s][0]);
        s_f[s][tid + 256] = geluf(hi2[s][1]);
    }
    __syncthreads();

    float dp[SPB];
    #pragma unroll
    for (int s = 0; s < SPB; s++) dp[s] = 0.0f;
    int j0 = hfi * 256;
    for (int jj = 0; jj < 256; jj++) {
        int j = j0 + jj;
        float wv = Wo[(size_t)j * Hv + c];
        #pragma unroll
        for (int s = 0; s < SPB; s++) dp[s] = fmaf(s_f[s][j], wv, dp[s]);
    }
    #pragma unroll
    for (int s = 0; s < SPB; s++) s_dp[hfi][s][c] = dp[s];
    __syncthreads();

    for (int s = 0; s < SPB; s++) {
        float x2 = 0.0f;
        if (hfi == 0) {
            x2 = s_h[s][c] + bo[c] + s_dp[0][s][c] + s_dp[1][s][c];
            float sum = x2, sq = x2 * x2;
            #pragma unroll
            for (int o = 16; o; o >>= 1) {
                sum += __shfl_xor_sync(0xffffffffu, sum, o);
                sq  += __shfl_xor_sync(0xffffffffu, sq, o);
            }
            if ((c & 31) == 0) { s_red[c >> 5] = sum; s_red[4 + (c >> 5)] = sq; }
        }
        __syncthreads();
        if (hfi == 0) {
            int site = base_site + s;
            float sum = s_red[0] + s_red[1] + s_red[2] + s_red[3];
            float sq  = s_red[4] + s_red[5] + s_red[6] + s_red[7];
            float mean = sum * (1.0f / Hv);
            float var  = sq * (1.0f / Hv) - mean * mean;
            float h2 = (x2 - mean) * rsqrtf(var + 1e-5f) * g2[c] + be2[c];
            out[(size_t)site * Hv + c] = maskV[site] * h2;
        }
        __syncthreads();
    }
}

// ---------------------------------------------------------------------------

extern "C" void kernel_launch(void* const* d_in, const int* in_sizes, int n_in,
                              void* d_out, int out_size) {
    const float* hV    = (const float*)d_in[0];
    const float* hE    = (const float*)d_in[1];
    const float* Xn    = (const float*)d_in[3];
    const float* maskV = (const float*)d_in[4];
    const float* maskA = (const float*)d_in[5];
    const float* Wp    = (const float*)d_in[6];
    const float* bp    = (const float*)d_in[7];
    const float* W1    = (const float*)d_in[8];
    const float* b1    = (const float*)d_in[9];
    const float* W2    = (const float*)d_in[10];
    const float* b2    = (const float*)d_in[11];
    const float* W3    = (const float*)d_in[12];
    const float* b3    = (const float*)d_in[13];
    const float* Wi    = (const float*)d_in[14];
    const float* bi    = (const float*)d_in[15];
    const float* Wo    = (const float*)d_in[16];
    const float* bo    = (const float*)d_in[17];
    const float* g1    = (const float*)d_in[18];
    const float* be1   = (const float*)d_in[19];
    const float* g2    = (const float*)d_in[20];
    const float* be2   = (const float*)d_in[21];
    float* out = (float*)d_out;

    cudaFuncSetAttribute(fusedgemm_kernel, cudaFuncAttributeMaxDynamicSharedMemorySize, GEMM_SMEM);
    cudaFuncSetAttribute(bias1_kernel, cudaFuncAttributeMaxDynamicSharedMemorySize, 66048);
    cudaFuncSetAttribute(geoFeat_kernel, cudaFuncAttributeMaxDynamicSharedMemorySize, GEOF_SMEM);

    static void *pFeat = nullptr, *pNM, *pB1, *pW1f, *pW2f, *pW3f;
    if (!pFeat) {
        cudaGetSymbolAddress(&pFeat, g_feat);
        cudaGetSymbolAddress(&pNM, g_nodem);
        cudaGetSymbolAddress(&pB1, g_bias1);
        cudaGetSymbolAddress(&pW1f, g_W1f);
        cudaGetSymbolAddress(&pW2f, g_W2f);
        cudaGetSymbolAddress(&pW3f, g_W3f);
    }

    wprep_kernel<<<(KA * Hv + 2 * Hv * Hv + 255) / 256, 256>>>(W1, W2, W3);
    bias1_kernel<<<512, 128, 66048>>>(hV, W1, b1);
    geoFeat_kernel<<<NSITE / 2, 256, GEOF_SMEM>>>(hE, Xn, Wp, bp);

    fusedgemm_kernel<<<MPAD / 128, 256, GEMM_SMEM>>>(
        hE, (const float*)pFeat,
        (const __half*)pW1f, (const __half*)pW2f, (const __half*)pW3f,
        (const float*)pB1, b2, b3, maskA, (float*)pNM);

    final_kernel<<<NSITE / SPB, 256>>>(hV, maskV, Wi, bi, Wo, bo,
                                       g1, be1, g2, be2, out);
}

// round 17
// speedup vs baseline: 1.3948x; 1.1424x over previous
#include <cuda_runtime.h>
#include <cuda_fp16.h>
#include <math.h>

#define Bv 8
#define Lv 512
#define Kv 30
#define Hv 128
#define NINv 384
#define EPSv 1e-8f

#define NSITE (Bv * Lv)          // 4096
#define MPAD (NSITE * 32)        // 131072 padded rows (32 edges/site)
#define KA 480
#define NCH 15                   // 480/32 k-chunks

// ------------------------- global scratch (static, no allocs) -------------
__device__ float g_feat[(size_t)MPAD * 96];
__device__ float g_nodem[(size_t)NSITE * Hv];
__device__ float g_bias1[(size_t)NSITE * Hv];
__device__ __half g_W1f[KA * Hv];
__device__ __half g_W2f[Hv * Hv];
__device__ __half g_W3f[Hv * Hv];
__device__ __half g_Wif[Hv * 512];
__device__ __half g_Wof[512 * Hv];

__device__ __forceinline__ float geluf(float x) {
    return 0.5f * x * (1.0f + erff(x * 0.7071067811865476f));
}
__device__ __forceinline__ unsigned pack2h(float a, float b) {
    __half2 v = __floats2half2_rn(a, b);
    return *(unsigned*)&v;
}

// ------------------------- small prep kernels -----------------------------
__global__ void wprep_kernel(const float* __restrict__ W1,
                             const float* __restrict__ W2,
                             const float* __restrict__ W3,
                             const float* __restrict__ Wi,
                             const float* __restrict__ Wo) {
    int idx = blockIdx.x * 256 + threadIdx.x;
    const int N1 = KA * Hv;                 // 61440
    const int N2 = N1 + Hv * Hv;            // +16384
    const int N3 = N2 + Hv * Hv;
    const int N4 = N3 + Hv * 512;           // +65536
    const int N5 = N4 + 512 * Hv;
    if (idx < N1) {
        int j = idx / Hv, c = idx % Hv;
        float v = (j < 456) ? W1[(Hv + j) * Hv + c] : 0.0f;
        g_W1f[idx] = __float2half_rn(v);
    } else if (idx < N2) {
        g_W2f[idx - N1] = __float2half_rn(W2[idx - N1]);
    } else if (idx < N3) {
        g_W3f[idx - N2] = __float2half_rn(W3[idx - N2]);
    } else if (idx < N4) {
        g_Wif[idx - N3] = __float2half_rn(Wi[idx - N3]);
    } else if (idx < N5) {
        g_Wof[idx - N4] = __float2half_rn(Wo[idx - N4]);
    }
}

__global__ __launch_bounds__(128) void bias1_kernel(const float* __restrict__ hV,
                                                    const float* __restrict__ W1,
                                                    const float* __restrict__ b1) {
    extern __shared__ float bsm[];
    float* sW = bsm;
    float* shv = bsm + 16384;
    int c = threadIdx.x;
    for (int i = c; i < 16384; i += 128) sW[i] = W1[i];
    __syncthreads();
    for (int site = blockIdx.x; site < NSITE; site += gridDim.x) {
        shv[c] = hV[(size_t)site * Hv + c];
        __syncthreads();
        float acc = b1[c];
        #pragma unroll 8
        for (int r = 0; r < Hv; r++) acc = fmaf(shv[r], sW[r * Hv + c], acc);
        g_bias1[(size_t)site * Hv + c] = acc;
        __syncthreads();
    }
}

__device__ __forceinline__ void make_frame(const float* __restrict__ x,
                                           float* __restrict__ R,
                                           float* __restrict__ t) {
    float Nx = x[0], Ny = x[1], Nz = x[2];
    float CAx = x[3], CAy = x[4], CAz = x[5];
    float Cx = x[6], Cy = x[7], Cz = x[8];
    float e0x = CAx - Nx, e0y = CAy - Ny, e0z = CAz - Nz;
    float inv = 1.0f / sqrtf(e0x * e0x + e0y * e0y + e0z * e0z + EPSv);
    e0x *= inv; e0y *= inv; e0z *= inv;
    float e1x = Cx - CAx, e1y = Cy - CAy, e1z = Cz - CAz;
    float d = e0x * e1x + e0y * e1y + e0z * e1z;
    e1x -= e0x * d; e1y -= e0y * d; e1z -= e0z * d;
    inv = 1.0f / sqrtf(e1x * e1x + e1y * e1y + e1z * e1z + EPSv);
    e1x *= inv; e1y *= inv; e1z *= inv;
    float e2x = e0y * e1z - e0z * e1y;
    float e2y = e0z * e1x - e0x * e1z;
    float e2z = e0x * e1y - e0y * e1x;
    R[0] = e0x; R[1] = e1x; R[2] = e2x;
    R[3] = e0y; R[4] = e1y; R[5] = e2y;
    R[6] = e0z; R[7] = e1z; R[8] = e2z;
    t[0] = CAx; t[1] = CAy; t[2] = CAz;
}

// ---------------------------------------------------------------------------
// geoFeat: 2 sites per block, 256 threads (unchanged)
// ---------------------------------------------------------------------------
#define GH_HVP  0
#define GH_PLN  3870
#define GH_R    4590
#define GH_T    4860
#define GH_NPG  4950
#define GH_FEAT 5670
#define GH_SIZE 7830
#define GEOF_SMEM ((3072 + 2 * GH_SIZE) * 4)

__global__ void __launch_bounds__(256) geoFeat_kernel(
    const float* __restrict__ hE, const float* __restrict__ Xn,
    const float* __restrict__ Wp, const float* __restrict__ bp)
{
    extern __shared__ float gs[];
    int tid = threadIdx.x;
    int hf = tid >> 7, t = tid & 127;
    int site = blockIdx.x * 2 + hf;
    float* WP = gs;
    float* base = gs + 3072 + hf * GH_SIZE;

    for (int i = tid; i < 3072; i += 256) WP[i] = Wp[i];
    for (int i = t; i < 30 * 128; i += 128) {
        int k = i >> 7, j = i & 127;
        base[GH_HVP + k * 129 + j] = hE[((size_t)(site * Kv + k)) * NINv + 256 + j];
    }
    if (t < Kv) make_frame(Xn + ((size_t)(site * Kv + t)) * 9,
                           base + GH_R + t * 9, base + GH_T + t * 3);
    __syncthreads();

    if (t < 120) {
        int k = t % 30, g = t / 30;
        float acc[6];
        #pragma unroll
        for (int j = 0; j < 6; j++) acc[j] = bp[g * 6 + j];
        const float* e = base + GH_HVP + k * 129;
        const float* wbase = WP + g * 6;
        #pragma unroll 4
        for (int i = 0; i < 128; i++) {
            float h = e[i];
            const float* wr = wbase + i * 24;
            float2 w01 = *(const float2*)(wr);
            float2 w23 = *(const float2*)(wr + 2);
            float2 w45 = *(const float2*)(wr + 4);
            acc[0] = fmaf(h, w01.x, acc[0]);
            acc[1] = fmaf(h, w01.y, acc[1]);
            acc[2] = fmaf(h, w23.x, acc[2]);
            acc[3] = fmaf(h, w23.y, acc[3]);
            acc[4] = fmaf(h, w45.x, acc[4]);
            acc[5] = fmaf(h, w45.y, acc[5]);
        }
        #pragma unroll
        for (int j = 0; j < 6; j++) base[GH_PLN + k * 24 + g * 6 + j] = acc[j];
    }
    __syncthreads();

    for (int p = t; p < 240; p += 128) {
        int k = p / 8, n = p % 8;
        const float* R = base + GH_R + k * 9;
        const float* tt = base + GH_T + k * 3;
        const float* pl = base + GH_PLN + k * 24 + n * 3;
        #pragma unroll
        for (int i = 0; i < 3; i++)
            base[GH_NPG + k * 24 + n * 3 + i] =
                tt[i] + R[i * 3] * pl[0] + R[i * 3 + 1] * pl[1] + R[i * 3 + 2] * pl[2];
    }
    __syncthreads();

    for (int p = t; p < 240; p += 128) {
        int k = p / 8, n = p % 8;
        float* f = base + GH_FEAT + k * 72;
        const float* pl0 = base + GH_PLN + n * 3;
        const float* pg  = base + GH_NPG + n * 3;
        const float* R0  = base + GH_R;
        const float* t0  = base + GH_T;
        const float* ng  = base + GH_NPG + k * 24 + n * 3;
        float p0 = pl0[0], p1 = pl0[1], p2 = pl0[2];
        f[n * 3] = p0; f[n * 3 + 1] = p1; f[n * 3 + 2] = p2;
        f[24 + n] = sqrtf(p0 * p0 + p1 * p1 + p2 * p2 + EPSv);
        float d0 = ng[0] - t0[0], d1 = ng[1] - t0[1], d2 = ng[2] - t0[2];
        float n0 = R0[0] * d0 + R0[3] * d1 + R0[6] * d2;
        float n1 = R0[1] * d0 + R0[4] * d1 + R0[7] * d2;
        float n2 = R0[2] * d0 + R0[5] * d1 + R0[8] * d2;
        f[32 + n * 3] = n0; f[32 + n * 3 + 1] = n1; f[32 + n * 3 + 2] = n2;
        f[56 + n] = sqrtf(n0 * n0 + n1 * n1 + n2 * n2 + EPSv);
        float gx = pg[0] - ng[0], gy = pg[1] - ng[1], gz = pg[2] - ng[2];
        f[64 + n] = sqrtf(gx * gx + gy * gy + gz * gz + EPSv);
    }
    __syncthreads();

    for (int i = t; i < 30 * 96; i += 128) {
        int k = i / 96, col = i - k * 96;
        float v = (col < 72) ? base[GH_FEAT + k * 72 + col] : 0.0f;
        g_feat[((size_t)(site * 32 + k)) * 96 + col] = v;
    }
}

// ---------------------------------------------------------------------------
// Fused GEMM + masked mean (unchanged from R12)
// ---------------------------------------------------------------------------
#define ABUF(i)  ((i) * 10240)
#define WST(i)   (20480 + (i) * 8704)
#define CT       0
#define OFF_W2   34816
#define GEMM_SMEM 69632

__device__ __forceinline__ void cpasync16(unsigned dst, const void* src) {
    asm volatile("cp.async.cg.shared.global [%0], [%1], 16;\n" :: "r"(dst), "l"(src));
}
__device__ __forceinline__ void ldm_x4(unsigned* r, unsigned addr) {
    asm volatile("ldmatrix.sync.aligned.m8n8.x4.shared.b16 {%0,%1,%2,%3}, [%4];"
        : "=r"(r[0]), "=r"(r[1]), "=r"(r[2]), "=r"(r[3]) : "r"(addr));
}
__device__ __forceinline__ void ldm_x4_t(unsigned* r, unsigned addr) {
    asm volatile("ldmatrix.sync.aligned.m8n8.x4.trans.shared.b16 {%0,%1,%2,%3}, [%4];"
        : "=r"(r[0]), "=r"(r[1]), "=r"(r[2]), "=r"(r[3]) : "r"(addr));
}
__device__ __forceinline__ void mma_f16(float* d, const unsigned* a, unsigned b0, unsigned b1) {
    asm volatile("mma.sync.aligned.m16n8k16.row.col.f32.f16.f16.f32 "
        "{%0,%1,%2,%3}, {%4,%5,%6,%7}, {%8,%9}, {%0,%1,%2,%3};"
        : "+f"(d[0]), "+f"(d[1]), "+f"(d[2]), "+f"(d[3])
        : "r"(a[0]), "r"(a[1]), "r"(a[2]), "r"(a[3]), "r"(b0), "r"(b1));
}
__device__ __forceinline__ void sts128(unsigned addr, const unsigned* v) {
    asm volatile("st.shared.v4.b32 [%0], {%1,%2,%3,%4};"
        :: "r"(addr), "r"(v[0]), "r"(v[1]), "r"(v[2]), "r"(v[3]));
}

__device__ __forceinline__ void wload_chunk(unsigned sbase, int st,
                                            const __half* __restrict__ W1f,
                                            int kc, int tid) {
    unsigned wst = sbase + WST(st);
    #pragma unroll
    for (int i = 0; i < 2; i++) {
        int tt = tid + i * 256;
        int rb = tt >> 4, sg = tt & 15;
        cpasync16(wst + (rb * 136 + sg * 8) * 2, W1f + (size_t)(kc + rb) * Hv + sg * 8);
    }
    asm volatile("cp.async.commit_group;\n" ::);
}
__device__ __forceinline__ void load_weight(unsigned sbase, unsigned off,
                                            const __half* __restrict__ src, int tid) {
    #pragma unroll
    for (int i = 0; i < 8; i++) {
        int idx = tid + i * 256;
        int r = idx >> 4, s = idx & 15;
        cpasync16(sbase + off + (r * 136 + s * 8) * 2, src + (size_t)r * Hv + s * 8);
    }
}

__global__ __launch_bounds__(256, 2) void fusedgemm_kernel(
    const float* __restrict__ hE, const float* __restrict__ feat,
    const __half* __restrict__ W1f, const __half* __restrict__ W2f,
    const __half* __restrict__ W3f,
    const float* __restrict__ bias1,
    const float* __restrict__ b2, const float* __restrict__ b3,
    const float* __restrict__ maskA,
    float* __restrict__ nodem)
{
    extern __shared__ __align__(16) unsigned char gsm[];
    unsigned sbase = (unsigned)__cvta_generic_to_shared(gsm);

    int tid = threadIdx.x;
    int lane = tid & 31, w = tid >> 5;
    int wm = w >> 1, wn = w & 1;
    int rowBase = blockIdx.x * 128;
    int site = blockIdx.x * 4 + wm;

    int arow = tid >> 1, half16 = tid & 1;
    int gr = rowBase + arow;
    int asite = gr >> 5;
    int ak = gr & 31; if (ak > 29) ak = 29;
    const float* hE_row = hE + ((size_t)(asite * Kv + ak)) * NINv + half16 * 16;
    const float* ft_row = feat + ((size_t)(asite * 32 + ak)) * 96 + half16 * 16;

    float4 f0, f1, f2, f3;
    #define LDA(cc) do { \
        const float4* s4 = (const float4*)(((cc) < 12) ? (hE_row + (cc) * 32) \
                                                       : (ft_row + ((cc) - 12) * 32)); \
        f0 = s4[0]; f1 = s4[1]; f2 = s4[2]; f3 = s4[3]; \
    } while (0)
    #define CVTSTS(buf) do { \
        unsigned uh[8]; \
        uh[0] = pack2h(f0.x, f0.y); uh[1] = pack2h(f0.z, f0.w); \
        uh[2] = pack2h(f1.x, f1.y); uh[3] = pack2h(f1.z, f1.w); \
        uh[4] = pack2h(f2.x, f2.y); uh[5] = pack2h(f2.z, f2.w); \
        uh[6] = pack2h(f3.x, f3.y); uh[7] = pack2h(f3.z, f3.w); \
        unsigned ab = sbase + ABUF(buf) + (unsigned)((arow * 40 + half16 * 16) * 2); \
        sts128(ab, uh); sts128(ab + 16, uh + 4); \
    } while (0)

    float acc[2][8][4];
    #pragma unroll
    for (int ma = 0; ma < 2; ma++)
        #pragma unroll
        for (int na = 0; na < 8; na++)
            #pragma unroll
            for (int q = 0; q < 4; q++) acc[ma][na][q] = 0.0f;

    wload_chunk(sbase, 0, W1f, 0, tid);
    wload_chunk(sbase, 1, W1f, 32, tid);
    LDA(0);
    CVTSTS(0);

    for (int c = 0; c < NCH; c++) {
        if (c + 1 < NCH) { asm volatile("cp.async.wait_group 1;\n" ::); }
        else             { asm volatile("cp.async.wait_group 0;\n" ::); }
        __syncthreads();

        if (c + 1 < NCH) LDA(c + 1);

        unsigned abuf = sbase + ABUF(c & 1);
        unsigned wst  = sbase + WST(c & 1);
        #pragma unroll
        for (int kk = 0; kk < 32; kk += 16) {
            unsigned aH[2][4];
            #pragma unroll
            for (int ma = 0; ma < 2; ma++) {
                int row = wm * 32 + ma * 16 + (lane & 15);
                unsigned off = (unsigned)((row * 40 + kk + ((lane >> 4) << 3)) * 2);
                ldm_x4(aH[ma], abuf + off);
            }
            #pragma unroll
            for (int nb = 0; nb < 4; nb++) {
                unsigned offb = (unsigned)(((kk + (lane & 15)) * 136 + wn * 64 + nb * 16 + ((lane >> 4) << 3)) * 2);
                unsigned bh[4];
                ldm_x4_t(bh, wst + offb);
                #pragma unroll
                for (int ma = 0; ma < 2; ma++) {
                    mma_f16(acc[ma][2 * nb],     aH[ma], bh[0], bh[1]);
                    mma_f16(acc[ma][2 * nb + 1], aH[ma], bh[2], bh[3]);
                }
            }
        }

        if (c + 1 < NCH) CVTSTS((c + 1) & 1);
        __syncthreads();
        if (c + 2 < NCH) wload_chunk(sbase, c & 1, W1f, (c + 2) * 32, tid);
    }

    load_weight(sbase, OFF_W2, W2f, tid);
    asm volatile("cp.async.commit_group;\n" ::);

    const float* bs = bias1 + (size_t)site * Hv;
    #pragma unroll
    for (int ma = 0; ma < 2; ma++)
        #pragma unroll
        for (int na = 0; na < 8; na++) {
            int row = wm * 32 + ma * 16 + (lane >> 2);
            int col = wn * 64 + na * 8 + ((lane & 3) << 1);
            float2 bb = *(const float2*)(bs + col);
            unsigned p0 = pack2h(geluf(acc[ma][na][0] + bb.x), geluf(acc[ma][na][1] + bb.y));
            unsigned p1 = pack2h(geluf(acc[ma][na][2] + bb.x), geluf(acc[ma][na][3] + bb.y));
            asm volatile("st.shared.b32 [%0], %1;" :: "r"(sbase + CT + (row * 136 + col) * 2), "r"(p0));
            asm volatile("st.shared.b32 [%0], %1;" :: "r"(sbase + CT + ((row + 8) * 136 + col) * 2), "r"(p1));
            acc[ma][na][0] = 0.0f; acc[ma][na][1] = 0.0f;
            acc[ma][na][2] = 0.0f; acc[ma][na][3] = 0.0f;
        }
    asm volatile("cp.async.wait_group 0;\n" ::);
    __syncthreads();

    #pragma unroll
    for (int q = 0; q < 8; q++) {
        unsigned aH[2][4];
        #pragma unroll
        for (int ma = 0; ma < 2; ma++) {
            int row = wm * 32 + ma * 16 + (lane & 15);
            unsigned off = (unsigned)((row * 136 + q * 16 + ((lane >> 4) << 3)) * 2);
            ldm_x4(aH[ma], sbase + CT + off);
        }
        #pragma unroll
        for (int nb = 0; nb < 4; nb++) {
            unsigned offb = (unsigned)(((q * 16 + (lane & 15)) * 136 + wn * 64 + nb * 16 + ((lane >> 4) << 3)) * 2);
            unsigned bh[4];
            ldm_x4_t(bh, sbase + OFF_W2 + offb);
            #pragma unroll
            for (int ma = 0; ma < 2; ma++) {
                mma_f16(acc[ma][2 * nb],     aH[ma], bh[0], bh[1]);
                mma_f16(acc[ma][2 * nb + 1], aH[ma], bh[2], bh[3]);
            }
        }
    }
    __syncthreads();
    load_weight(sbase, OFF_W2, W3f, tid);
    asm volatile("cp.async.commit_group;\n" ::);

    #pragma unroll
    for (int ma = 0; ma < 2; ma++)
        #pragma unroll
        for (int na = 0; na < 8; na++) {
            int row = wm * 32 + ma * 16 + (lane >> 2);
            int col = wn * 64 + na * 8 + ((lane & 3) << 1);
            float2 bb = *(const float2*)(b2 + col);
            unsigned p0 = pack2h(geluf(acc[ma][na][0] + bb.x), geluf(acc[ma][na][1] + bb.y));
            unsigned p1 = pack2h(geluf(acc[ma][na][2] + bb.x), geluf(acc[ma][na][3] + bb.y));
            asm volatile("st.shared.b32 [%0], %1;" :: "r"(sbase + CT + (row * 136 + col) * 2), "r"(p0));
            asm volatile("st.shared.b32 [%0], %1;" :: "r"(sbase + CT + ((row + 8) * 136 + col) * 2), "r"(p1));
            acc[ma][na][0] = 0.0f; acc[ma][na][1] = 0.0f;
            acc[ma][na][2] = 0.0f; acc[ma][na][3] = 0.0f;
        }
    asm volatile("cp.async.wait_group 0;\n" ::);
    __syncthreads();

    #pragma unroll
    for (int q = 0; q < 8; q++) {
        unsigned aH[2][4];
        #pragma unroll
        for (int ma = 0; ma < 2; ma++) {
            int row = wm * 32 + ma * 16 + (lane & 15);
            unsigned off = (unsigned)((row * 136 + q * 16 + ((lane >> 4) << 3)) * 2);
            ldm_x4(aH[ma], sbase + CT + off);
        }
        #pragma unroll
        for (int nb = 0; nb < 4; nb++) {
            unsigned offb = (unsigned)(((q * 16 + (lane & 15)) * 136 + wn * 64 + nb * 16 + ((lane >> 4) << 3)) * 2);
            unsigned bh[4];
            ldm_x4_t(bh, sbase + OFF_W2 + offb);
            #pragma unroll
            for (int ma = 0; ma < 2; ma++) {
                mma_f16(acc[ma][2 * nb],     aH[ma], bh[0], bh[1]);
                mma_f16(acc[ma][2 * nb + 1], aH[ma], bh[2], bh[3]);
            }
        }
    }

    {
        const float* mrow = maskA + (size_t)site * Kv;
        int gq = lane >> 2;
        float wgt[2][2];
        #pragma unroll
        for (int ma = 0; ma < 2; ma++)
            #pragma unroll
            for (int h = 0; h < 2; h++) {
                int rk = ma * 16 + gq + h * 8;
                wgt[ma][h] = (rk < Kv) ? mrow[rk] : 0.0f;
            }
        float colsum[16];
        #pragma unroll
        for (int na = 0; na < 8; na++) {
            int col = wn * 64 + na * 8 + ((lane & 3) << 1);
            float2 bb = *(const float2*)(b3 + col);
            float s0 = 0.0f, s1 = 0.0f;
            #pragma unroll
            for (int ma = 0; ma < 2; ma++) {
                s0 += wgt[ma][0] * (acc[ma][na][0] + bb.x) + wgt[ma][1] * (acc[ma][na][2] + bb.x);
                s1 += wgt[ma][0] * (acc[ma][na][1] + bb.y) + wgt[ma][1] * (acc[ma][na][3] + bb.y);
            }
            colsum[2 * na] = s0;
            colsum[2 * na + 1] = s1;
        }
        #pragma unroll
        for (int j = 0; j < 16; j++) {
            float s = colsum[j];
            s += __shfl_xor_sync(0xffffffffu, s, 4);
            s += __shfl_xor_sync(0xffffffffu, s, 8);
            s += __shfl_xor_sync(0xffffffffu, s, 16);
            colsum[j] = s;
        }
        if (lane < 4) {
            #pragma unroll
            for (int na = 0; na < 8; na++) {
                int col = wn * 64 + na * 8 + lane * 2;
                float2 v;
                v.x = colsum[2 * na] * (1.0f / (float)Kv);
                v.y = colsum[2 * na + 1] * (1.0f / (float)Kv);
                *(float2*)(nodem + (size_t)site * Hv + col) = v;
            }
        }
    }
}

// ---------------------------------------------------------------------------
// final_mma: 32 sites/block, LN1 fp32 -> FFN on tensor cores (fp16 weights)
//            -> LN2 fp32 -> masked out. grid = 128 blocks, 256 threads.
// smem bytes:
//   [0, 8704)        h fp16 tile [32][136]
//   [8704, 41984)    Wi stages 2 x (16 x 520 halves) ; later C1 tile [32][520]
//   [41984, 59392)   Wo stages 2 x (32 x 136 halves) ; later d fp32 [32][128]
//   [59392, 75776)   h fp32 [32][128]
// ---------------------------------------------------------------------------
#define FS_H16   0
#define FS_WI(i) (8704 + (i) * 16640)
#define FS_C1    8704
#define FS_WO(i) (41984 + (i) * 8704)
#define FS_D     41984
#define FS_F32   59392
#define FINAL_SMEM 75776

__global__ __launch_bounds__(256) void final_mma(
    const float* __restrict__ hV, const float* __restrict__ maskV,
    const __half* __restrict__ WiF, const float* __restrict__ bi,
    const __half* __restrict__ WoF, const float* __restrict__ bo,
    const float* __restrict__ g1, const float* __restrict__ be1,
    const float* __restrict__ g2, const float* __restrict__ be2,
    float* __restrict__ out)
{
    extern __shared__ __align__(16) unsigned char fsm[];
    unsigned sbase = (unsigned)__cvta_generic_to_shared(fsm);
    float* smf = (float*)fsm;

    int tid = threadIdx.x;
    int lane = tid & 31, w = tid >> 5;
    int siteBase = blockIdx.x * 32;

    // ---- LN1: warp w handles sites 4w..4w+3; lane covers cols lane*4.. ----
    #pragma unroll
    for (int i = 0; i < 4; i++) {
        int s = w * 4 + i;
        int site = siteBase + s;
        int col = lane * 4;
        float4 xv = *(const float4*)(hV + (size_t)site * Hv + col);
        float4 nm = *(const float4*)(g_nodem + (size_t)site * Hv + col);
        xv.x += nm.x; xv.y += nm.y; xv.z += nm.z; xv.w += nm.w;
        float sum = xv.x + xv.y + xv.z + xv.w;
        float sq  = xv.x * xv.x + xv.y * xv.y + xv.z * xv.z + xv.w * xv.w;
        #pragma unroll
        for (int o = 16; o; o >>= 1) {
            sum += __shfl_xor_sync(0xffffffffu, sum, o);
            sq  += __shfl_xor_sync(0xffffffffu, sq, o);
        }
        float mean = sum * (1.0f / Hv);
        float var  = sq * (1.0f / Hv) - mean * mean;
        float rstd = rsqrtf(var + 1e-5f);
        float4 gg = *(const float4*)(g1 + col);
        float4 be = *(const float4*)(be1 + col);
        float h0 = (xv.x - mean) * rstd * gg.x + be.x;
        float h1 = (xv.y - mean) * rstd * gg.y + be.y;
        float h2 = (xv.z - mean) * rstd * gg.z + be.z;
        float h3 = (xv.w - mean) * rstd * gg.w + be.w;
        unsigned p0 = pack2h(h0, h1), p1 = pack2h(h2, h3);
        unsigned ha = sbase + FS_H16 + (unsigned)((s * 136 + col) * 2);
        asm volatile("st.shared.v2.b32 [%0], {%1,%2};" :: "r"(ha), "r"(p0), "r"(p1));
        float4 hv4; hv4.x = h0; hv4.y = h1; hv4.z = h2; hv4.w = h3;
        *(float4*)(smf + (FS_F32 >> 2) + s * Hv + col) = hv4;
    }
    __syncthreads();

    // ---- FFN1: M=32, N=512, K=128. warp w owns cols 64w..64w+63 ----
    {
        // prologue: Wi chunks 0,1
        #pragma unroll
        for (int st = 0; st < 2; st++) {
            #pragma unroll
            for (int i_ = 0; i_ < 4; i_++) {
                int seg = tid + i_ * 256;
                int r_ = seg >> 6, sg_ = seg & 63;
                cpasync16(sbase + FS_WI(st) + (unsigned)((r_ * 520 + sg_ * 8) * 2),
                          WiF + (size_t)(st * 16 + r_) * 512 + sg_ * 8);
            }
            asm volatile("cp.async.commit_group;\n" ::);
        }

        float acc[2][8][4];
        #pragma unroll
        for (int ma = 0; ma < 2; ma++)
            #pragma unroll
            for (int na = 0; na < 8; na++)
                #pragma unroll
                for (int q = 0; q < 4; q++) acc[ma][na][q] = 0.0f;

        for (int c = 0; c < 8; c++) {
            if (c + 1 < 8) { asm volatile("cp.async.wait_group 1;\n" ::); }
            else           { asm volatile("cp.async.wait_group 0;\n" ::); }
            __syncthreads();
            unsigned wst = sbase + FS_WI(c & 1);
            unsigned aH[2][4];
            #pragma unroll
            for (int ma = 0; ma < 2; ma++) {
                int row = ma * 16 + (lane & 15);
                unsigned off = (unsigned)((row * 136 + c * 16 + ((lane >> 4) << 3)) * 2);
                ldm_x4(aH[ma], sbase + FS_H16 + off);
            }
            #pragma unroll
            for (int nb = 0; nb < 4; nb++) {
                unsigned offb = (unsigned)(((lane & 15) * 520 + w * 64 + nb * 16 + ((lane >> 4) << 3)) * 2);
                unsigned bh[4];
                ldm_x4_t(bh, wst + offb);
                #pragma unroll
                for (int ma = 0; ma < 2; ma++) {
                    mma_f16(acc[ma][2 * nb],     aH[ma], bh[0], bh[1]);
                    mma_f16(acc[ma][2 * nb + 1], aH[ma], bh[2], bh[3]);
                }
            }
            __syncthreads();
            if (c + 2 < 8) {
                int cc = c + 2;
                #pragma unroll
                for (int i_ = 0; i_ < 4; i_++) {
                    int seg = tid + i_ * 256;
                    int r_ = seg >> 6, sg_ = seg & 63;
                    cpasync16(sbase + FS_WI(c & 1) + (unsigned)((r_ * 520 + sg_ * 8) * 2),
                              WiF + (size_t)(cc * 16 + r_) * 512 + sg_ * 8);
                }
                asm volatile("cp.async.commit_group;\n" ::);
            }
        }

        // kick off Wo chunks 0,1 (separate region)
        #pragma unroll
        for (int st = 0; st < 2; st++) {
            #pragma unroll
            for (int i_ = 0; i_ < 2; i_++) {
                int seg = tid + i_ * 256;
                int r_ = seg >> 4, sg_ = seg & 15;
                cpasync16(sbase + FS_WO(st) + (unsigned)((r_ * 136 + sg_ * 8) * 2),
                          WoF + (size_t)(st * 32 + r_) * Hv + sg_ * 8);
            }
            asm volatile("cp.async.commit_group;\n" ::);
        }
        __syncthreads();   // all FFN1 MMA reads done before C1 overwrites stages

        // C1 = gelu(acc + bi) -> fp16 tile [32][520]
        #pragma unroll
        for (int ma = 0; ma < 2; ma++)
            #pragma unroll
            for (int na = 0; na < 8; na++) {
                int r0 = ma * 16 + (lane >> 2);
                int col = w * 64 + na * 8 + ((lane & 3) << 1);
                float2 bb = *(const float2*)(bi + col);
                unsigned p0 = pack2h(geluf(acc[ma][na][0] + bb.x), geluf(acc[ma][na][1] + bb.y));
                unsigned p1 = pack2h(geluf(acc[ma][na][2] + bb.x), geluf(acc[ma][na][3] + bb.y));
                asm volatile("st.shared.b32 [%0], %1;"
                    :: "r"(sbase + FS_C1 + (unsigned)((r0 * 520 + col) * 2)), "r"(p0));
                asm volatile("st.shared.b32 [%0], %1;"
                    :: "r"(sbase + FS_C1 + (unsigned)(((r0 + 8) * 520 + col) * 2)), "r"(p1));
            }
    }

    // ---- FFN2: M=32, N=128, K=512. warp w owns cols 16w..16w+15 ----
    {
        float acc2[2][2][4];
        #pragma unroll
        for (int ma = 0; ma < 2; ma++)
            #pragma unroll
            for (int na = 0; na < 2; na++)
                #pragma unroll
                for (int q = 0; q < 4; q++) acc2[ma][na][q] = 0.0f;

        for (int c = 0; c < 16; c++) {
            if (c + 1 < 16) { asm volatile("cp.async.wait_group 1;\n" ::); }
            else            { asm volatile("cp.async.wait_group 0;\n" ::); }
            __syncthreads();
            unsigned wst = sbase + FS_WO(c & 1);
            #pragma unroll
            for (int kk = 0; kk < 32; kk += 16) {
                unsigned aH[2][4];
                #pragma unroll
                for (int ma = 0; ma < 2; ma++) {
                    int row = ma * 16 + (lane & 15);
                    int colk = c * 32 + kk + ((lane >> 4) << 3);
                    ldm_x4(aH[ma], sbase + FS_C1 + (unsigned)((row * 520 + colk) * 2));
                }
                unsigned offb = (unsigned)(((kk + (lane & 15)) * 136 + w * 16 + ((lane >> 4) << 3)) * 2);
                unsigned bh[4];
                ldm_x4_t(bh, wst + offb);
                #pragma unroll
                for (int ma = 0; ma < 2; ma++) {
                    mma_f16(acc2[ma][0], aH[ma], bh[0], bh[1]);
                    mma_f16(acc2[ma][1], aH[ma], bh[2], bh[3]);
                }
            }
            __syncthreads();
            if (c + 2 < 16) {
                int cc = c + 2;
                #pragma unroll
                for (int i_ = 0; i_ < 2; i_++) {
                    int seg = tid + i_ * 256;
                    int r_ = seg >> 4, sg_ = seg & 15;
                    cpasync16(sbase + FS_WO(c & 1) + (unsigned)((r_ * 136 + sg_ * 8) * 2),
                              WoF + (size_t)(cc * 32 + r_) * Hv + sg_ * 8);
                }
                asm volatile("cp.async.commit_group;\n" ::);
            }
        }
        __syncthreads();   // Wo stages dead -> d region safe

        // d = acc2 + bo -> fp32 [32][128] in FS_D
        #pragma unroll
        for (int ma = 0; ma < 2; ma++)
            #pragma unroll
            for (int na = 0; na < 2; na++) {
                int r0 = ma * 16 + (lane >> 2);
                int col = w * 16 + na * 8 + ((lane & 3) << 1);
                float2 bb = *(const float2*)(bo + col);
                float2 v0; v0.x = acc2[ma][na][0] + bb.x; v0.y = acc2[ma][na][1] + bb.y;
                float2 v1; v1.x = acc2[ma][na][2] + bb.x; v1.y = acc2[ma][na][3] + bb.y;
                *(float2*)(smf + (FS_D >> 2) + r0 * Hv + col) = v0;
                *(float2*)(smf + (FS_D >> 2) + (r0 + 8) * Hv + col) = v1;
            }
        __syncthreads();
    }

    // ---- LN2 + masked output ----
    #pragma unroll
    for (int i = 0; i < 4; i++) {
        int s = w * 4 + i;
        int site = siteBase + s;
        int col = lane * 4;
        float4 hv4 = *(const float4*)(smf + (FS_F32 >> 2) + s * Hv + col);
        float4 dv4 = *(const float4*)(smf + (FS_D >> 2) + s * Hv + col);
        float4 x2;
        x2.x = hv4.x + dv4.x; x2.y = hv4.y + dv4.y;
        x2.z = hv4.z + dv4.z; x2.w = hv4.w + dv4.w;
        float sum = x2.x + x2.y + x2.z + x2.w;
        float sq  = x2.x * x2.x + x2.y * x2.y + x2.z * x2.z + x2.w * x2.w;
        #pragma unroll
        for (int o = 16; o; o >>= 1) {
            sum += __shfl_xor_sync(0xffffffffu, sum, o);
            sq  += __shfl_xor_sync(0xffffffffu, sq, o);
        }
        float mean = sum * (1.0f / Hv);
        float var  = sq * (1.0f / Hv) - mean * mean;
        float rstd = rsqrtf(var + 1e-5f);
        float mv = maskV[site];
        float4 gg = *(const float4*)(g2 + col);
        float4 be = *(const float4*)(be2 + col);
        float4 o4;
        o4.x = mv * ((x2.x - mean) * rstd * gg.x + be.x);
        o4.y = mv * ((x2.y - mean) * rstd * gg.y + be.y);
        o4.z = mv * ((x2.z - mean) * rstd * gg.z + be.z);
        o4.w = mv * ((x2.w - mean) * rstd * gg.w + be.w);
        *(float4*)(out + (size_t)site * Hv + col) = o4;
    }
}

// ---------------------------------------------------------------------------

extern "C" void kernel_launch(void* const* d_in, const int* in_sizes, int n_in,
                              void* d_out, int out_size) {
    const float* hV    = (const float*)d_in[0];
    const float* hE    = (const float*)d_in[1];
    const float* Xn    = (const float*)d_in[3];
    const float* maskV = (const float*)d_in[4];
    const float* maskA = (const float*)d_in[5];
    const float* Wp    = (const float*)d_in[6];
    const float* bp    = (const float*)d_in[7];
    const float* W1    = (const float*)d_in[8];
    const float* b1    = (const float*)d_in[9];
    const float* W2    = (const float*)d_in[10];
    const float* b2    = (const float*)d_in[11];
    const float* W3    = (const float*)d_in[12];
    const float* b3    = (const float*)d_in[13];
    const float* Wi    = (const float*)d_in[14];
    const float* bi    = (const float*)d_in[15];
    const float* Wo    = (const float*)d_in[16];
    const float* bo    = (const float*)d_in[17];
    const float* g1    = (const float*)d_in[18];
    const float* be1   = (const float*)d_in[19];
    const float* g2    = (const float*)d_in[20];
    const float* be2   = (const float*)d_in[21];
    float* out = (float*)d_out;

    cudaFuncSetAttribute(fusedgemm_kernel, cudaFuncAttributeMaxDynamicSharedMemorySize, GEMM_SMEM);
    cudaFuncSetAttribute(bias1_kernel, cudaFuncAttributeMaxDynamicSharedMemorySize, 66048);
    cudaFuncSetAttribute(geoFeat_kernel, cudaFuncAttributeMaxDynamicSharedMemorySize, GEOF_SMEM);
    cudaFuncSetAttribute(final_mma, cudaFuncAttributeMaxDynamicSharedMemorySize, FINAL_SMEM);

    static void *pFeat = nullptr, *pNM, *pB1, *pW1f, *pW2f, *pW3f, *pWif, *pWof;
    if (!pFeat) {
        cudaGetSymbolAddress(&pFeat, g_feat);
        cudaGetSymbolAddress(&pNM, g_nodem);
        cudaGetSymbolAddress(&pB1, g_bias1);
        cudaGetSymbolAddress(&pW1f, g_W1f);
        cudaGetSymbolAddress(&pW2f, g_W2f);
        cudaGetSymbolAddress(&pW3f, g_W3f);
        cudaGetSymbolAddress(&pWif, g_Wif);
        cudaGetSymbolAddress(&pWof, g_Wof);
    }

    const int wtot = KA * Hv + 2 * Hv * Hv + 2 * 512 * Hv;
    wprep_kernel<<<(wtot + 255) / 256, 256>>>(W1, W2, W3, Wi, Wo);
    bias1_kernel<<<512, 128, 66048>>>(hV, W1, b1);
    geoFeat_kernel<<<NSITE / 2, 256, GEOF_SMEM>>>(hE, Xn, Wp, bp);

    fusedgemm_kernel<<<MPAD / 128, 256, GEMM_SMEM>>>(
        hE, (const float*)pFeat,
        (const __half*)pW1f, (const __half*)pW2f, (const __half*)pW3f,
        (const float*)pB1, b2, b3, maskA, (float*)pNM);

    final_mma<<<NSITE / 32, 256, FINAL_SMEM>>>(
        hV, maskV, (const __half*)pWif, bi, (const __half*)pWof, bo,
        g1, be1, g2, be2, out);
}